// round 1
// baseline (speedup 1.0000x reference)
#include <cuda_runtime.h>

#define Bb 2
#define Ss 2048
#define Dd 1024
#define Hh 16
#define DK 64
#define BH (Bb*Hh)       // 32
#define MROWS (Bb*Ss)    // 4096

// Scratch (allocation-free rule: __device__ globals)
__device__ float g_qh[(size_t)BH * Ss * DK];   // [B,H,S,dk] 16MB
__device__ float g_kh[(size_t)BH * Ss * DK];
__device__ float g_vh[(size_t)BH * Ss * DK];
__device__ float g_ctx[(size_t)Bb * Ss * Dd];  // [B,S,D] 16MB

// ---------------------------------------------------------------------------
// GEMM: Y = X @ W + b.  X:[4096,1024] W:[1024,1024] row-major.
// SPLIT=true  -> write head-split layout [B,H,S,dk]
// SPLIT=false -> write row-major [4096,1024]
// 64x64 tile, 256 threads, 4x4 microtile, K-tile 16.
// ---------------------------------------------------------------------------
template <bool SPLIT>
__global__ void __launch_bounds__(256) gemm_bias_kernel(
    const float* __restrict__ X, const float* __restrict__ W,
    const float* __restrict__ bias, float* __restrict__ Y)
{
    __shared__ float As[16][65];   // [k][m] (transposed on load)
    __shared__ float Bs[16][64];   // [k][n]

    const int tx = threadIdx.x;
    const int m0 = blockIdx.y * 64;
    const int n0 = blockIdx.x * 64;
    const int tr = tx >> 4;        // 0..15
    const int tc = tx & 15;        // 0..15

    // A-load mapping: each thread one float4 along K
    const int a_m = tx >> 2;          // 0..63
    const int a_k = (tx & 3) << 2;    // 0,4,8,12
    // B-load mapping: each thread one float4 along N
    const int b_k = tx >> 4;          // 0..15
    const int b_n = (tx & 15) << 2;   // 0..60

    float acc[4][4] = {};

    for (int k0 = 0; k0 < Dd; k0 += 16) {
        float4 av = *(const float4*)&X[(size_t)(m0 + a_m) * Dd + k0 + a_k];
        As[a_k + 0][a_m] = av.x;
        As[a_k + 1][a_m] = av.y;
        As[a_k + 2][a_m] = av.z;
        As[a_k + 3][a_m] = av.w;
        *(float4*)&Bs[b_k][b_n] =
            *(const float4*)&W[(size_t)(k0 + b_k) * Dd + n0 + b_n];
        __syncthreads();

        #pragma unroll
        for (int kk = 0; kk < 16; kk++) {
            float a[4], b[4];
            #pragma unroll
            for (int i = 0; i < 4; i++) a[i] = As[kk][tr * 4 + i];
            float4 bv = *(const float4*)&Bs[kk][tc * 4];
            b[0] = bv.x; b[1] = bv.y; b[2] = bv.z; b[3] = bv.w;
            #pragma unroll
            for (int i = 0; i < 4; i++)
                #pragma unroll
                for (int j = 0; j < 4; j++)
                    acc[i][j] = fmaf(a[i], b[j], acc[i][j]);
        }
        __syncthreads();
    }

    #pragma unroll
    for (int i = 0; i < 4; i++) {
        const int m = m0 + tr * 4 + i;
        #pragma unroll
        for (int j = 0; j < 4; j++) {
            const int n = n0 + tc * 4 + j;
            const float y = acc[i][j] + bias[n];
            if (SPLIT) {
                const int b = m >> 11;       // /Ss
                const int s = m & (Ss - 1);
                const int h = n >> 6;        // /DK
                const int dc = n & (DK - 1);
                Y[(((size_t)(b * Hh + h)) * Ss + s) * DK + dc] = y;
            } else {
                Y[(size_t)m * Dd + n] = y;
            }
        }
    }
}

// ---------------------------------------------------------------------------
// Scores: per (b,h): S[q,k] = (Qh[q,:] . Kh[k,:]) * 0.125   (dk=64 fully in smem)
// 64x64 tile, 256 threads, 4x4 microtile.
// ---------------------------------------------------------------------------
__global__ void __launch_bounds__(256) scores_kernel(
    const float* __restrict__ Qh, const float* __restrict__ Kh,
    float* __restrict__ attn)
{
    const int bh = blockIdx.z;
    const float* Q = Qh + (size_t)bh * Ss * DK;
    const float* K = Kh + (size_t)bh * Ss * DK;
    float* O = attn + (size_t)bh * Ss * Ss;

    __shared__ float Qs[64][65];
    __shared__ float Ks[64][65];

    const int tx = threadIdx.x;
    const int q0 = blockIdx.y * 64;
    const int k0 = blockIdx.x * 64;

    #pragma unroll
    for (int j = 0; j < 4; j++) {
        const int idx4 = tx + j * 256;       // 0..1023 float4 slots
        const int row = idx4 >> 4;           // 0..63
        const int c = (idx4 & 15) << 2;      // 0..60
        float4 qv = *(const float4*)&Q[(size_t)(q0 + row) * DK + c];
        Qs[row][c + 0] = qv.x; Qs[row][c + 1] = qv.y;
        Qs[row][c + 2] = qv.z; Qs[row][c + 3] = qv.w;
        float4 kv = *(const float4*)&K[(size_t)(k0 + row) * DK + c];
        Ks[row][c + 0] = kv.x; Ks[row][c + 1] = kv.y;
        Ks[row][c + 2] = kv.z; Ks[row][c + 3] = kv.w;
    }
    __syncthreads();

    const int tr = tx >> 4;
    const int tc = tx & 15;
    float acc[4][4] = {};

    #pragma unroll 8
    for (int k = 0; k < 64; k++) {
        float a[4], b[4];
        #pragma unroll
        for (int i = 0; i < 4; i++) a[i] = Qs[tr * 4 + i][k];
        #pragma unroll
        for (int j = 0; j < 4; j++) b[j] = Ks[tc * 4 + j][k];
        #pragma unroll
        for (int i = 0; i < 4; i++)
            #pragma unroll
            for (int j = 0; j < 4; j++)
                acc[i][j] = fmaf(a[i], b[j], acc[i][j]);
    }

    #pragma unroll
    for (int i = 0; i < 4; i++)
        #pragma unroll
        for (int j = 0; j < 4; j++)
            O[(size_t)(q0 + tr * 4 + i) * Ss + (k0 + tc * 4 + j)] =
                acc[i][j] * 0.125f;
}

// ---------------------------------------------------------------------------
// In-place row softmax over attn: one 256-thread block per row of 2048.
// ---------------------------------------------------------------------------
__global__ void __launch_bounds__(256) softmax_kernel(float* __restrict__ attn)
{
    float* p = attn + (size_t)blockIdx.x * Ss;
    const int tx = threadIdx.x;
    const int lane = tx & 31, wid = tx >> 5;

    float v[8];
    float4 a = ((const float4*)p)[tx * 2 + 0];
    float4 b = ((const float4*)p)[tx * 2 + 1];
    v[0] = a.x; v[1] = a.y; v[2] = a.z; v[3] = a.w;
    v[4] = b.x; v[5] = b.y; v[6] = b.z; v[7] = b.w;

    __shared__ float red[8];

    float mx = v[0];
    #pragma unroll
    for (int i = 1; i < 8; i++) mx = fmaxf(mx, v[i]);
    #pragma unroll
    for (int o = 16; o; o >>= 1) mx = fmaxf(mx, __shfl_xor_sync(~0u, mx, o));
    if (lane == 0) red[wid] = mx;
    __syncthreads();
    mx = red[0];
    #pragma unroll
    for (int i = 1; i < 8; i++) mx = fmaxf(mx, red[i]);
    __syncthreads();

    float s = 0.f;
    #pragma unroll
    for (int i = 0; i < 8; i++) { v[i] = __expf(v[i] - mx); s += v[i]; }
    #pragma unroll
    for (int o = 16; o; o >>= 1) s += __shfl_xor_sync(~0u, s, o);
    if (lane == 0) red[wid] = s;
    __syncthreads();
    s = red[0];
    #pragma unroll
    for (int i = 1; i < 8; i++) s += red[i];
    const float inv = 1.0f / s;

    float4 oa = make_float4(v[0] * inv, v[1] * inv, v[2] * inv, v[3] * inv);
    float4 ob = make_float4(v[4] * inv, v[5] * inv, v[6] * inv, v[7] * inv);
    ((float4*)p)[tx * 2 + 0] = oa;
    ((float4*)p)[tx * 2 + 1] = ob;
}

// ---------------------------------------------------------------------------
// ctx: per (b,h): C[S,64] = P[S,S] @ V[S,64]; write into [B,S,D] layout.
// Block tile 128x64, 256 threads, 8x4 microtile, K-tile 32.
// ---------------------------------------------------------------------------
__global__ void __launch_bounds__(256) ctx_kernel(
    const float* __restrict__ attn, const float* __restrict__ Vh,
    float* __restrict__ ctx)
{
    const int bh = blockIdx.z;
    const int b = bh >> 4;       // /Hh
    const int h = bh & (Hh - 1);
    const float* P = attn + (size_t)bh * Ss * Ss;
    const float* V = Vh + (size_t)bh * Ss * DK;

    __shared__ float Ps[128][33];
    __shared__ float Vs[32][65];

    const int tx = threadIdx.x;
    const int m0 = blockIdx.y * 128;
    const int tr = tx >> 4;      // 0..15 -> rows tr*8..tr*8+7
    const int tc = tx & 15;      // cols tc*4..tc*4+3

    float acc[8][4] = {};

    for (int kt = 0; kt < Ss; kt += 32) {
        #pragma unroll
        for (int j = 0; j < 4; j++) {
            const int idx4 = tx + j * 256;     // 1024 float4 = 128x32
            const int row = idx4 >> 3;
            const int c = (idx4 & 7) << 2;
            float4 pv = *(const float4*)&P[(size_t)(m0 + row) * Ss + kt + c];
            Ps[row][c + 0] = pv.x; Ps[row][c + 1] = pv.y;
            Ps[row][c + 2] = pv.z; Ps[row][c + 3] = pv.w;
        }
        #pragma unroll
        for (int j = 0; j < 2; j++) {
            const int idx4 = tx + j * 256;     // 512 float4 = 32x64
            const int row = idx4 >> 4;
            const int c = (idx4 & 15) << 2;
            float4 vv = *(const float4*)&V[(size_t)(kt + row) * DK + c];
            Vs[row][c + 0] = vv.x; Vs[row][c + 1] = vv.y;
            Vs[row][c + 2] = vv.z; Vs[row][c + 3] = vv.w;
        }
        __syncthreads();

        #pragma unroll 8
        for (int kk = 0; kk < 32; kk++) {
            float bv[4];
            #pragma unroll
            for (int j = 0; j < 4; j++) bv[j] = Vs[kk][tc * 4 + j];
            #pragma unroll
            for (int i = 0; i < 8; i++) {
                const float av = Ps[tr * 8 + i][kk];
                #pragma unroll
                for (int j = 0; j < 4; j++)
                    acc[i][j] = fmaf(av, bv[j], acc[i][j]);
            }
        }
        __syncthreads();
    }

    #pragma unroll
    for (int i = 0; i < 8; i++) {
        const int s = m0 + tr * 8 + i;
        #pragma unroll
        for (int j = 0; j < 4; j++)
            ctx[((size_t)(b * Ss + s)) * Dd + h * DK + tc * 4 + j] = acc[i][j];
    }
}

// ---------------------------------------------------------------------------
extern "C" void kernel_launch(void* const* d_in, const int* in_sizes, int n_in,
                              void* d_out, int out_size)
{
    const float* q   = (const float*)d_in[0];
    const float* k   = (const float*)d_in[1];
    const float* v   = (const float*)d_in[2];
    const float* W_q = (const float*)d_in[3];
    const float* b_q = (const float*)d_in[4];
    const float* W_k = (const float*)d_in[5];
    const float* b_k = (const float*)d_in[6];
    const float* W_v = (const float*)d_in[7];
    const float* b_v = (const float*)d_in[8];
    const float* W_o = (const float*)d_in[9];
    const float* b_o = (const float*)d_in[10];

    float* out  = (float*)d_out;                        // [B,S,D]
    float* attn = out + (size_t)Bb * Ss * Dd;           // [B,H,S,S]

    float* qh;  cudaGetSymbolAddress((void**)&qh,  g_qh);
    float* kh;  cudaGetSymbolAddress((void**)&kh,  g_kh);
    float* vh;  cudaGetSymbolAddress((void**)&vh,  g_vh);
    float* ctx; cudaGetSymbolAddress((void**)&ctx, g_ctx);

    dim3 gproj(Dd / 64, MROWS / 64);                    // (16, 64)
    gemm_bias_kernel<true><<<gproj, 256>>>(q, W_q, b_q, qh);
    gemm_bias_kernel<true><<<gproj, 256>>>(k, W_k, b_k, kh);
    gemm_bias_kernel<true><<<gproj, 256>>>(v, W_v, b_v, vh);

    dim3 gsc(Ss / 64, Ss / 64, BH);                     // (32, 32, 32)
    scores_kernel<<<gsc, 256>>>(qh, kh, attn);

    softmax_kernel<<<BH * Ss, 256>>>(attn);             // 65536 rows

    dim3 gctx(1, Ss / 128, BH);                         // (1, 16, 32)
    ctx_kernel<<<gctx, 256>>>(attn, vh, ctx);

    gemm_bias_kernel<false><<<gproj, 256>>>(ctx, W_o, b_o, out);
}

// round 2
// speedup vs baseline: 1.2779x; 1.2779x over previous
#include <cuda_runtime.h>

#define Bb 2
#define Ss 2048
#define Dd 1024
#define Hh 16
#define DK 64
#define BH (Bb*Hh)       // 32
#define MROWS (Bb*Ss)    // 4096

// Scratch (allocation-free rule: __device__ globals)
__device__ float g_qh[(size_t)BH * Ss * DK];   // [B,H,S,dk]
__device__ float g_kh[(size_t)BH * Ss * DK];
__device__ float g_vh[(size_t)BH * Ss * DK];
__device__ float g_ctx[(size_t)Bb * Ss * Dd];  // [B,S,D]

// ---- packed f32x2 helpers (FFMA2: only reachable via PTX) ----
__device__ __forceinline__ unsigned long long pack2(float x) {
    unsigned long long r;
    asm("mov.b64 %0, {%1, %1};" : "=l"(r) : "f"(x));
    return r;
}
__device__ __forceinline__ void fma2(unsigned long long& d,
                                     unsigned long long a,
                                     unsigned long long b) {
    asm("fma.rn.f32x2 %0, %1, %2, %0;" : "+l"(d) : "l"(a), "l"(b));
}
__device__ __forceinline__ float2 unpack2(unsigned long long v) {
    float2 f;
    asm("mov.b64 {%0, %1}, %2;" : "=f"(f.x), "=f"(f.y) : "l"(v));
    return f;
}

// ---------------------------------------------------------------------------
// QKV projection GEMM, batched over z: Y = X @ W + b, X:[4096,1024] W:[1024,1024]
// 128x128 tile, kt=32, 256 threads, 8x8 microtile, f32x2 FMA.
// Writes head-split layout [B,H,S,dk].
// ---------------------------------------------------------------------------
__global__ void __launch_bounds__(256) qkv_gemm_kernel(
    const float* __restrict__ q, const float* __restrict__ k, const float* __restrict__ v,
    const float* __restrict__ Wq, const float* __restrict__ Wk, const float* __restrict__ Wv,
    const float* __restrict__ bq, const float* __restrict__ bk, const float* __restrict__ bv,
    float* __restrict__ Yq, float* __restrict__ Yk, float* __restrict__ Yv)
{
    const int z = blockIdx.z;
    const float* X    = (z == 0) ? q  : (z == 1) ? k  : v;
    const float* W    = (z == 0) ? Wq : (z == 1) ? Wk : Wv;
    const float* bias = (z == 0) ? bq : (z == 1) ? bk : bv;
    float* Y          = (z == 0) ? Yq : (z == 1) ? Yk : Yv;

    __shared__ float As[32][132];   // [k][m]
    __shared__ float Bs[32][132];   // [k][n]

    const int tx = threadIdx.x;
    const int m0 = blockIdx.y * 128;
    const int n0 = blockIdx.x * 128;
    const int tr = tx >> 4;   // 0..15 -> rows tr*8
    const int tc = tx & 15;   // 0..15 -> cols tc*8

    unsigned long long acc[8][4];
    #pragma unroll
    for (int i = 0; i < 8; i++)
        #pragma unroll
        for (int j = 0; j < 4; j++) acc[i][j] = 0ull;

    for (int k0 = 0; k0 < Dd; k0 += 32) {
        // A tile 128x32, transpose into As[k][m]
        #pragma unroll
        for (int j = 0; j < 4; j++) {
            const int idx4 = tx + j * 256;
            const int row = idx4 >> 3;
            const int c = (idx4 & 7) << 2;
            float4 av = *(const float4*)&X[(size_t)(m0 + row) * Dd + k0 + c];
            As[c + 0][row] = av.x; As[c + 1][row] = av.y;
            As[c + 2][row] = av.z; As[c + 3][row] = av.w;
        }
        // B tile 32x128 direct
        #pragma unroll
        for (int j = 0; j < 4; j++) {
            const int idx4 = tx + j * 256;
            const int bk = idx4 >> 5;
            const int bn = (idx4 & 31) << 2;
            *(float4*)&Bs[bk][bn] =
                *(const float4*)&W[(size_t)(k0 + bk) * Dd + n0 + bn];
        }
        __syncthreads();

        #pragma unroll 8
        for (int kk = 0; kk < 32; kk++) {
            float4 a0 = *(const float4*)&As[kk][tr * 8];
            float4 a1 = *(const float4*)&As[kk][tr * 8 + 4];
            ulonglong2 b0 = *(const ulonglong2*)&Bs[kk][tc * 8];
            ulonglong2 b1 = *(const ulonglong2*)&Bs[kk][tc * 8 + 4];
            unsigned long long bb[4] = {b0.x, b0.y, b1.x, b1.y};
            float av[8] = {a0.x, a0.y, a0.z, a0.w, a1.x, a1.y, a1.z, a1.w};
            #pragma unroll
            for (int i = 0; i < 8; i++) {
                unsigned long long aa = pack2(av[i]);
                fma2(acc[i][0], aa, bb[0]);
                fma2(acc[i][1], aa, bb[1]);
                fma2(acc[i][2], aa, bb[2]);
                fma2(acc[i][3], aa, bb[3]);
            }
        }
        __syncthreads();
    }

    // epilogue: bias + head-split store (8 contiguous cols never cross a head)
    const int nbase = n0 + tc * 8;
    float4 bi0 = *(const float4*)&bias[nbase];
    float4 bi1 = *(const float4*)&bias[nbase + 4];
    const int h = nbase >> 6;
    const int dc = nbase & (DK - 1);
    #pragma unroll
    for (int i = 0; i < 8; i++) {
        const int m = m0 + tr * 8 + i;
        const int b = m >> 11;
        const int s = m & (Ss - 1);
        float2 p0 = unpack2(acc[i][0]);
        float2 p1 = unpack2(acc[i][1]);
        float2 p2 = unpack2(acc[i][2]);
        float2 p3 = unpack2(acc[i][3]);
        float4 y0 = make_float4(p0.x + bi0.x, p0.y + bi0.y, p1.x + bi0.z, p1.y + bi0.w);
        float4 y1 = make_float4(p2.x + bi1.x, p2.y + bi1.y, p3.x + bi1.z, p3.y + bi1.w);
        float* dst = &Y[(((size_t)(b * Hh + h)) * Ss + s) * DK + dc];
        *(float4*)dst = y0;
        *(float4*)(dst + 4) = y1;
    }
}

// ---------------------------------------------------------------------------
// Output GEMM: out = ctx @ W_o + b_o, row-major store.
// ---------------------------------------------------------------------------
__global__ void __launch_bounds__(256) out_gemm_kernel(
    const float* __restrict__ X, const float* __restrict__ W,
    const float* __restrict__ bias, float* __restrict__ Y)
{
    __shared__ float As[32][132];
    __shared__ float Bs[32][132];

    const int tx = threadIdx.x;
    const int m0 = blockIdx.y * 128;
    const int n0 = blockIdx.x * 128;
    const int tr = tx >> 4;
    const int tc = tx & 15;

    unsigned long long acc[8][4];
    #pragma unroll
    for (int i = 0; i < 8; i++)
        #pragma unroll
        for (int j = 0; j < 4; j++) acc[i][j] = 0ull;

    for (int k0 = 0; k0 < Dd; k0 += 32) {
        #pragma unroll
        for (int j = 0; j < 4; j++) {
            const int idx4 = tx + j * 256;
            const int row = idx4 >> 3;
            const int c = (idx4 & 7) << 2;
            float4 av = *(const float4*)&X[(size_t)(m0 + row) * Dd + k0 + c];
            As[c + 0][row] = av.x; As[c + 1][row] = av.y;
            As[c + 2][row] = av.z; As[c + 3][row] = av.w;
        }
        #pragma unroll
        for (int j = 0; j < 4; j++) {
            const int idx4 = tx + j * 256;
            const int bk = idx4 >> 5;
            const int bn = (idx4 & 31) << 2;
            *(float4*)&Bs[bk][bn] =
                *(const float4*)&W[(size_t)(k0 + bk) * Dd + n0 + bn];
        }
        __syncthreads();

        #pragma unroll 8
        for (int kk = 0; kk < 32; kk++) {
            float4 a0 = *(const float4*)&As[kk][tr * 8];
            float4 a1 = *(const float4*)&As[kk][tr * 8 + 4];
            ulonglong2 b0 = *(const ulonglong2*)&Bs[kk][tc * 8];
            ulonglong2 b1 = *(const ulonglong2*)&Bs[kk][tc * 8 + 4];
            unsigned long long bb[4] = {b0.x, b0.y, b1.x, b1.y};
            float av[8] = {a0.x, a0.y, a0.z, a0.w, a1.x, a1.y, a1.z, a1.w};
            #pragma unroll
            for (int i = 0; i < 8; i++) {
                unsigned long long aa = pack2(av[i]);
                fma2(acc[i][0], aa, bb[0]);
                fma2(acc[i][1], aa, bb[1]);
                fma2(acc[i][2], aa, bb[2]);
                fma2(acc[i][3], aa, bb[3]);
            }
        }
        __syncthreads();
    }

    const int nbase = n0 + tc * 8;
    float4 bi0 = *(const float4*)&bias[nbase];
    float4 bi1 = *(const float4*)&bias[nbase + 4];
    #pragma unroll
    for (int i = 0; i < 8; i++) {
        const int m = m0 + tr * 8 + i;
        float2 p0 = unpack2(acc[i][0]);
        float2 p1 = unpack2(acc[i][1]);
        float2 p2 = unpack2(acc[i][2]);
        float2 p3 = unpack2(acc[i][3]);
        float4 y0 = make_float4(p0.x + bi0.x, p0.y + bi0.y, p1.x + bi0.z, p1.y + bi0.w);
        float4 y1 = make_float4(p2.x + bi1.x, p2.y + bi1.y, p3.x + bi1.z, p3.y + bi1.w);
        float* dst = &Y[(size_t)m * Dd + nbase];
        *(float4*)dst = y0;
        *(float4*)(dst + 4) = y1;
    }
}

// ---------------------------------------------------------------------------
// Scores: per (b,h): S[q,k] = (Qh[q,:].Kh[k,:]) * 0.125
// 128x128 tile, 256 threads, 8x8 microtile, dk=64 in 2 chunks of 32.
// ---------------------------------------------------------------------------
__global__ void __launch_bounds__(256) scores_kernel(
    const float* __restrict__ Qh, const float* __restrict__ Kh,
    float* __restrict__ attn)
{
    const int bh = blockIdx.z;
    const float* Q = Qh + (size_t)bh * Ss * DK;
    const float* K = Kh + (size_t)bh * Ss * DK;
    float* O = attn + (size_t)bh * Ss * Ss;

    __shared__ float Qs[32][132];   // [k][q]
    __shared__ float Ks[32][132];   // [k][kcol]

    const int tx = threadIdx.x;
    const int q0 = blockIdx.y * 128;
    const int k0 = blockIdx.x * 128;
    const int tr = tx >> 4;
    const int tc = tx & 15;

    unsigned long long acc[8][4];
    #pragma unroll
    for (int i = 0; i < 8; i++)
        #pragma unroll
        for (int j = 0; j < 4; j++) acc[i][j] = 0ull;

    #pragma unroll
    for (int kc = 0; kc < DK; kc += 32) {
        #pragma unroll
        for (int j = 0; j < 4; j++) {
            const int idx4 = tx + j * 256;
            const int row = idx4 >> 3;
            const int c = (idx4 & 7) << 2;
            float4 qv = *(const float4*)&Q[(size_t)(q0 + row) * DK + kc + c];
            Qs[c + 0][row] = qv.x; Qs[c + 1][row] = qv.y;
            Qs[c + 2][row] = qv.z; Qs[c + 3][row] = qv.w;
            float4 kv = *(const float4*)&K[(size_t)(k0 + row) * DK + kc + c];
            Ks[c + 0][row] = kv.x; Ks[c + 1][row] = kv.y;
            Ks[c + 2][row] = kv.z; Ks[c + 3][row] = kv.w;
        }
        __syncthreads();

        #pragma unroll 8
        for (int kk = 0; kk < 32; kk++) {
            float4 a0 = *(const float4*)&Qs[kk][tr * 8];
            float4 a1 = *(const float4*)&Qs[kk][tr * 8 + 4];
            ulonglong2 b0 = *(const ulonglong2*)&Ks[kk][tc * 8];
            ulonglong2 b1 = *(const ulonglong2*)&Ks[kk][tc * 8 + 4];
            unsigned long long bb[4] = {b0.x, b0.y, b1.x, b1.y};
            float av[8] = {a0.x, a0.y, a0.z, a0.w, a1.x, a1.y, a1.z, a1.w};
            #pragma unroll
            for (int i = 0; i < 8; i++) {
                unsigned long long aa = pack2(av[i]);
                fma2(acc[i][0], aa, bb[0]);
                fma2(acc[i][1], aa, bb[1]);
                fma2(acc[i][2], aa, bb[2]);
                fma2(acc[i][3], aa, bb[3]);
            }
        }
        __syncthreads();
    }

    #pragma unroll
    for (int i = 0; i < 8; i++) {
        float2 p0 = unpack2(acc[i][0]);
        float2 p1 = unpack2(acc[i][1]);
        float2 p2 = unpack2(acc[i][2]);
        float2 p3 = unpack2(acc[i][3]);
        float4 y0 = make_float4(p0.x * 0.125f, p0.y * 0.125f, p1.x * 0.125f, p1.y * 0.125f);
        float4 y1 = make_float4(p2.x * 0.125f, p2.y * 0.125f, p3.x * 0.125f, p3.y * 0.125f);
        float* dst = &O[(size_t)(q0 + tr * 8 + i) * Ss + k0 + tc * 8];
        *(float4*)dst = y0;
        *(float4*)(dst + 4) = y1;
    }
}

// ---------------------------------------------------------------------------
// In-place row softmax: one 256-thread block per row of 2048.
// ---------------------------------------------------------------------------
__global__ void __launch_bounds__(256) softmax_kernel(float* __restrict__ attn)
{
    float* p = attn + (size_t)blockIdx.x * Ss;
    const int tx = threadIdx.x;
    const int lane = tx & 31, wid = tx >> 5;

    float v[8];
    float4 a = ((const float4*)p)[tx * 2 + 0];
    float4 b = ((const float4*)p)[tx * 2 + 1];
    v[0] = a.x; v[1] = a.y; v[2] = a.z; v[3] = a.w;
    v[4] = b.x; v[5] = b.y; v[6] = b.z; v[7] = b.w;

    __shared__ float red[8];

    float mx = v[0];
    #pragma unroll
    for (int i = 1; i < 8; i++) mx = fmaxf(mx, v[i]);
    #pragma unroll
    for (int o = 16; o; o >>= 1) mx = fmaxf(mx, __shfl_xor_sync(~0u, mx, o));
    if (lane == 0) red[wid] = mx;
    __syncthreads();
    mx = red[0];
    #pragma unroll
    for (int i = 1; i < 8; i++) mx = fmaxf(mx, red[i]);
    __syncthreads();

    float s = 0.f;
    #pragma unroll
    for (int i = 0; i < 8; i++) { v[i] = __expf(v[i] - mx); s += v[i]; }
    #pragma unroll
    for (int o = 16; o; o >>= 1) s += __shfl_xor_sync(~0u, s, o);
    if (lane == 0) red[wid] = s;
    __syncthreads();
    s = red[0];
    #pragma unroll
    for (int i = 1; i < 8; i++) s += red[i];
    const float inv = 1.0f / s;

    ((float4*)p)[tx * 2 + 0] = make_float4(v[0] * inv, v[1] * inv, v[2] * inv, v[3] * inv);
    ((float4*)p)[tx * 2 + 1] = make_float4(v[4] * inv, v[5] * inv, v[6] * inv, v[7] * inv);
}

// ---------------------------------------------------------------------------
// ctx: per (b,h): C[S,64] = P[S,S] @ V[S,64]; write [B,S,D] layout.
// 256x64 tile, kt=32, 256 threads (32x8), 8x8 microtile.
// ---------------------------------------------------------------------------
__global__ void __launch_bounds__(256) ctx_kernel(
    const float* __restrict__ attn, const float* __restrict__ Vh,
    float* __restrict__ ctx)
{
    const int bh = blockIdx.z;
    const int b = bh >> 4;
    const int h = bh & (Hh - 1);
    const float* P = attn + (size_t)bh * Ss * Ss;
    const float* V = Vh + (size_t)bh * Ss * DK;

    __shared__ float Ps[32][260];   // [k][m], m=256
    __shared__ float Vs[32][68];    // [k][n], n=64

    const int tx = threadIdx.x;
    const int m0 = blockIdx.y * 256;
    const int tr = tx >> 3;   // 0..31 -> rows tr*8
    const int tc = tx & 7;    // 0..7  -> cols tc*8

    unsigned long long acc[8][4];
    #pragma unroll
    for (int i = 0; i < 8; i++)
        #pragma unroll
        for (int j = 0; j < 4; j++) acc[i][j] = 0ull;

    for (int kt = 0; kt < Ss; kt += 32) {
        #pragma unroll
        for (int j = 0; j < 8; j++) {
            const int idx4 = tx + j * 256;      // 2048 float4 = 256x32
            const int row = idx4 >> 3;
            const int c = (idx4 & 7) << 2;
            float4 pv = *(const float4*)&P[(size_t)(m0 + row) * Ss + kt + c];
            Ps[c + 0][row] = pv.x; Ps[c + 1][row] = pv.y;
            Ps[c + 2][row] = pv.z; Ps[c + 3][row] = pv.w;
        }
        #pragma unroll
        for (int j = 0; j < 2; j++) {
            const int idx4 = tx + j * 256;      // 512 float4 = 32x64
            const int row = idx4 >> 4;
            const int c = (idx4 & 15) << 2;
            *(float4*)&Vs[row][c] = *(const float4*)&V[(size_t)(kt + row) * DK + c];
        }
        __syncthreads();

        #pragma unroll 8
        for (int kk = 0; kk < 32; kk++) {
            float4 a0 = *(const float4*)&Ps[kk][tr * 8];
            float4 a1 = *(const float4*)&Ps[kk][tr * 8 + 4];
            ulonglong2 b0 = *(const ulonglong2*)&Vs[kk][tc * 8];
            ulonglong2 b1 = *(const ulonglong2*)&Vs[kk][tc * 8 + 4];
            unsigned long long bb[4] = {b0.x, b0.y, b1.x, b1.y};
            float av[8] = {a0.x, a0.y, a0.z, a0.w, a1.x, a1.y, a1.z, a1.w};
            #pragma unroll
            for (int i = 0; i < 8; i++) {
                unsigned long long aa = pack2(av[i]);
                fma2(acc[i][0], aa, bb[0]);
                fma2(acc[i][1], aa, bb[1]);
                fma2(acc[i][2], aa, bb[2]);
                fma2(acc[i][3], aa, bb[3]);
            }
        }
        __syncthreads();
    }

    #pragma unroll
    for (int i = 0; i < 8; i++) {
        const int s = m0 + tr * 8 + i;
        float2 p0 = unpack2(acc[i][0]);
        float2 p1 = unpack2(acc[i][1]);
        float2 p2 = unpack2(acc[i][2]);
        float2 p3 = unpack2(acc[i][3]);
        float* dst = &ctx[((size_t)(b * Ss + s)) * Dd + h * DK + tc * 8];
        *(float4*)dst = make_float4(p0.x, p0.y, p1.x, p1.y);
        *(float4*)(dst + 4) = make_float4(p2.x, p2.y, p3.x, p3.y);
    }
}

// ---------------------------------------------------------------------------
extern "C" void kernel_launch(void* const* d_in, const int* in_sizes, int n_in,
                              void* d_out, int out_size)
{
    const float* q   = (const float*)d_in[0];
    const float* k   = (const float*)d_in[1];
    const float* v   = (const float*)d_in[2];
    const float* W_q = (const float*)d_in[3];
    const float* b_q = (const float*)d_in[4];
    const float* W_k = (const float*)d_in[5];
    const float* b_k = (const float*)d_in[6];
    const float* W_v = (const float*)d_in[7];
    const float* b_v = (const float*)d_in[8];
    const float* W_o = (const float*)d_in[9];
    const float* b_o = (const float*)d_in[10];

    float* out  = (float*)d_out;                 // [B,S,D]
    float* attn = out + (size_t)Bb * Ss * Dd;    // [B,H,S,S]

    float* qh;  cudaGetSymbolAddress((void**)&qh,  g_qh);
    float* kh;  cudaGetSymbolAddress((void**)&kh,  g_kh);
    float* vh;  cudaGetSymbolAddress((void**)&vh,  g_vh);
    float* ctx; cudaGetSymbolAddress((void**)&ctx, g_ctx);

    dim3 gqkv(Dd / 128, MROWS / 128, 3);         // (8, 32, 3)
    qkv_gemm_kernel<<<gqkv, 256>>>(q, k, v, W_q, W_k, W_v, b_q, b_k, b_v,
                                   qh, kh, vh);

    dim3 gsc(Ss / 128, Ss / 128, BH);            // (16, 16, 32)
    scores_kernel<<<gsc, 256>>>(qh, kh, attn);

    softmax_kernel<<<BH * Ss, 256>>>(attn);      // 65536 rows

    dim3 gctx(1, Ss / 256, BH);                  // (1, 8, 32)
    ctx_kernel<<<gctx, 256>>>(attn, vh, ctx);

    dim3 gout(Dd / 128, MROWS / 128, 1);         // (8, 32)
    out_gemm_kernel<<<gout, 256>>>(ctx, W_o, b_o, out);
}

// round 6
// speedup vs baseline: 1.9465x; 1.5233x over previous
#include <cuda_runtime.h>
#include <cuda_bf16.h>
#include <cstdint>

#define Bb 2
#define Ss 2048
#define Dd 1024
#define Hh 16
#define DK 64
#define BH (Bb*Hh)       // 32
#define MROWS (Bb*Ss)    // 4096

// ---------------- device scratch (allocation-free rule) ----------------
__device__ __nv_bfloat16 g_wt_hi[4][(size_t)Dd * Dd];   // W^T [N,K] bf16 hi
__device__ __nv_bfloat16 g_wt_lo[4][(size_t)Dd * Dd];
__device__ __nv_bfloat16 g_qh_hi[(size_t)BH * Ss * DK]; // head-split [BH,S,dk]
__device__ __nv_bfloat16 g_qh_lo[(size_t)BH * Ss * DK];
__device__ __nv_bfloat16 g_kh_hi[(size_t)BH * Ss * DK];
__device__ __nv_bfloat16 g_kh_lo[(size_t)BH * Ss * DK];
__device__ __nv_bfloat16 g_vh_hi[(size_t)BH * Ss * DK];
__device__ __nv_bfloat16 g_vh_lo[(size_t)BH * Ss * DK];
__device__ __nv_bfloat16 g_vt_hi[(size_t)BH * DK * Ss]; // V^T [BH,dk,S]
__device__ __nv_bfloat16 g_vt_lo[(size_t)BH * DK * Ss];
__device__ __nv_bfloat16 g_ctx_hi[(size_t)MROWS * Dd];  // ctx [4096,1024]
__device__ __nv_bfloat16 g_ctx_lo[(size_t)MROWS * Dd];

// ---------------- helpers ----------------
__device__ __forceinline__ uint32_t smem_u32(const void* p) {
    uint32_t a;
    asm("{ .reg .u64 t; cvta.to.shared.u64 t, %1; cvt.u32.u64 %0, t; }" : "=r"(a) : "l"(p));
    return a;
}
__device__ __forceinline__ uint32_t pk2(float a, float b) {   // lo=a, hi=b
    uint32_t r;
    asm("cvt.rn.bf16x2.f32 %0, %1, %2;" : "=r"(r) : "f"(b), "f"(a));
    return r;
}
__device__ __forceinline__ void split4(float4 x, uint2& hi, uint2& lo) {
    uint32_t h0 = pk2(x.x, x.y), h1 = pk2(x.z, x.w);
    float a0 = __uint_as_float(h0 << 16), a1 = __uint_as_float(h0 & 0xFFFF0000u);
    float a2 = __uint_as_float(h1 << 16), a3 = __uint_as_float(h1 & 0xFFFF0000u);
    hi = make_uint2(h0, h1);
    lo = make_uint2(pk2(x.x - a0, x.y - a1), pk2(x.z - a2, x.w - a3));
}
__device__ __forceinline__ void ldm_x4(uint32_t (&r)[4], uint32_t addr) {
    asm volatile("ldmatrix.sync.aligned.m8n8.x4.shared.b16 {%0,%1,%2,%3}, [%4];"
        : "=r"(r[0]), "=r"(r[1]), "=r"(r[2]), "=r"(r[3]) : "r"(addr));
}
__device__ __forceinline__ void mma_bf16(float (&c)[4], const uint32_t (&a)[4],
                                         uint32_t b0, uint32_t b1) {
    asm volatile("mma.sync.aligned.m16n8k16.row.col.f32.bf16.bf16.f32 "
        "{%0,%1,%2,%3}, {%4,%5,%6,%7}, {%8,%9}, {%0,%1,%2,%3};"
        : "+f"(c[0]), "+f"(c[1]), "+f"(c[2]), "+f"(c[3])
        : "r"(a[0]), "r"(a[1]), "r"(a[2]), "r"(a[3]), "r"(b0), "r"(b1));
}

#define STRIDE 80   // bytes per 32-bf16 smem row (64B data + 16B pad; conflict-free)

// warp tile 32x(16*NP) one k16 step; hi/lo 3-product scheme
template <int NP>
__device__ __forceinline__ void wtile_k16(
    float (&c)[2][2 * NP][4],
    uint32_t aH, uint32_t aL, uint32_t bH, uint32_t bL,
    int wm0, int wn0, int ks, uint32_t laneOfs)
{
    uint32_t ah[2][4], al[2][4], bh[NP][4], bl[NP][4];
    #pragma unroll
    for (int mf = 0; mf < 2; mf++) {
        ldm_x4(ah[mf], aH + (wm0 + mf * 16) * STRIDE + ks * 2 + laneOfs);
        ldm_x4(al[mf], aL + (wm0 + mf * 16) * STRIDE + ks * 2 + laneOfs);
    }
    #pragma unroll
    for (int np = 0; np < NP; np++) {
        ldm_x4(bh[np], bH + (wn0 + np * 16) * STRIDE + ks * 2 + laneOfs);
        ldm_x4(bl[np], bL + (wn0 + np * 16) * STRIDE + ks * 2 + laneOfs);
    }
    #pragma unroll
    for (int mf = 0; mf < 2; mf++)
        #pragma unroll
        for (int np = 0; np < NP; np++) {
            mma_bf16(c[mf][2 * np],     ah[mf], bh[np][0], bh[np][2]);
            mma_bf16(c[mf][2 * np + 1], ah[mf], bh[np][1], bh[np][3]);
            mma_bf16(c[mf][2 * np],     ah[mf], bl[np][0], bl[np][2]);
            mma_bf16(c[mf][2 * np + 1], ah[mf], bl[np][1], bl[np][3]);
            mma_bf16(c[mf][2 * np],     al[mf], bh[np][0], bh[np][2]);
            mma_bf16(c[mf][2 * np + 1], al[mf], bh[np][1], bh[np][3]);
        }
}

// ===========================================================================
// prep_w: W[K,N] fp32 -> Wt hi/lo [N,K] bf16.  grid (16, 32, 4), 256 thr
// ===========================================================================
__global__ void __launch_bounds__(256) prep_w_kernel(
    const float* __restrict__ W0, const float* __restrict__ W1,
    const float* __restrict__ W2, const float* __restrict__ W3)
{
    const float* Wz[4] = {W0, W1, W2, W3};
    const float* W = Wz[blockIdx.z];
    uint32_t* out_hi = (uint32_t*)g_wt_hi[blockIdx.z];
    uint32_t* out_lo = (uint32_t*)g_wt_lo[blockIdx.z];

    __shared__ float ts[64][33];
    const int k0 = blockIdx.x * 64, n0 = blockIdx.y * 32, tx = threadIdx.x;

    #pragma unroll
    for (int j = 0; j < 8; j++) {
        const int idx = tx + j * 256;
        const int k = idx >> 5, n = idx & 31;
        ts[k][n] = W[(size_t)(k0 + k) * Dd + n0 + n];
    }
    __syncthreads();

    #pragma unroll
    for (int j = 0; j < 4; j++) {
        const int idx = tx + j * 256;
        const int n = idx >> 5, kp = idx & 31;
        float f0 = ts[2 * kp][n], f1 = ts[2 * kp + 1][n];
        uint32_t h = pk2(f0, f1);
        float a0 = __uint_as_float(h << 16), a1 = __uint_as_float(h & 0xFFFF0000u);
        uint32_t l = pk2(f0 - a0, f1 - a1);
        const size_t o = (size_t)(n0 + n) * (Dd / 2) + (k0 >> 1) + kp;
        out_hi[o] = h;
        out_lo[o] = l;
    }
}

// ===========================================================================
// qkv: Y = X@W + b -> head-split bf16 hi/lo. grid (8 nt, 32 mt, 3), 512 thr
// ===========================================================================
__global__ void __launch_bounds__(512) qkv_mma_kernel(
    const float* __restrict__ q, const float* __restrict__ k, const float* __restrict__ v,
    const float* __restrict__ bq, const float* __restrict__ bk, const float* __restrict__ bv)
{
    __shared__ char sm[40960];   // AH 0, AL 10240, BH 20480, BL 30720
    const uint32_t sb = smem_u32(sm);
    const uint32_t aH = sb, aL = sb + 10240, bHs = sb + 20480, bLs = sb + 30720;

    const int z = blockIdx.z;
    const float* X    = (z == 0) ? q  : (z == 1) ? k  : v;
    const float* bias = (z == 0) ? bq : (z == 1) ? bk : bv;
    const char* WtH = (const char*)g_wt_hi[z];
    const char* WtL = (const char*)g_wt_lo[z];
    char* Y_hi = (char*)((z == 0) ? g_qh_hi : (z == 1) ? g_kh_hi : g_vh_hi);
    char* Y_lo = (char*)((z == 0) ? g_qh_lo : (z == 1) ? g_kh_lo : g_vh_lo);

    const int tx = threadIdx.x, w = tx >> 5, lane = tx & 31;
    const int n0 = blockIdx.x * 128, m0 = blockIdx.y * 128;
    const int wm0 = (w & 3) * 32, wn0 = (w >> 2) * 32;
    const uint32_t laneOfs = (lane & 15) * STRIDE + (lane >> 4) * 16;

    float c[2][4][4] = {};

    for (int k0 = 0; k0 < Dd; k0 += 32) {
        // A: fp32 -> split bf16, 128x32
        #pragma unroll
        for (int j = 0; j < 2; j++) {
            const int idx = tx + j * 512;
            const int row = idx >> 3, cc = (idx & 7) * 4;
            float4 x = *(const float4*)&X[(size_t)(m0 + row) * Dd + k0 + cc];
            uint2 hi, lo;
            split4(x, hi, lo);
            *(uint2*)(sm + 0     + row * STRIDE + cc * 2) = hi;
            *(uint2*)(sm + 10240 + row * STRIDE + cc * 2) = lo;
        }
        // B: bf16 copy, 128 rows x 64B
        {
            const int row = tx >> 2, cb = (tx & 3) * 16;
            const size_t bo = (size_t)(n0 + row) * (Dd * 2) + k0 * 2 + cb;
            *(uint4*)(sm + 20480 + row * STRIDE + cb) = *(const uint4*)(WtH + bo);
            *(uint4*)(sm + 30720 + row * STRIDE + cb) = *(const uint4*)(WtL + bo);
        }
        __syncthreads();
        wtile_k16<2>(c, aH, aL, bHs, bLs, wm0, wn0, 0, laneOfs);
        wtile_k16<2>(c, aH, aL, bHs, bLs, wm0, wn0, 16, laneOfs);
        __syncthreads();
    }

    // epilogue: bias + head-split hi/lo store
    const int g = lane >> 2, t2 = (lane & 3) * 2;
    #pragma unroll
    for (int mf = 0; mf < 2; mf++)
        #pragma unroll
        for (int nf = 0; nf < 4; nf++) {
            const int n = n0 + wn0 + nf * 8 + t2;
            const int h = n >> 6, dc = n & (DK - 1);
            const float bf0 = bias[n], bf1 = bias[n + 1];
            #pragma unroll
            for (int rr = 0; rr < 2; rr++) {
                const int m = m0 + wm0 + mf * 16 + g + rr * 8;
                const int bb = m >> 11, s = m & (Ss - 1);
                float f0 = c[mf][nf][2 * rr] + bf0;
                float f1 = c[mf][nf][2 * rr + 1] + bf1;
                uint32_t hw = pk2(f0, f1);
                float a0 = __uint_as_float(hw << 16), a1 = __uint_as_float(hw & 0xFFFF0000u);
                uint32_t lw = pk2(f0 - a0, f1 - a1);
                const size_t eo = ((((size_t)(bb * Hh + h)) * Ss + s) * DK + dc) * 2;
                *(uint32_t*)(Y_hi + eo) = hw;
                *(uint32_t*)(Y_lo + eo) = lw;
            }
        }
}

// ===========================================================================
// vt transpose: vh [bh,s,dk] -> vt [bh,dk,s]. grid (32 st, 2 dkt, 32 bh), 256 thr
// ===========================================================================
__global__ void __launch_bounds__(256) vt_kernel()
{
    __shared__ unsigned short th[64][34];
    __shared__ unsigned short tl[64][34];
    const int s0 = blockIdx.x * 64, dk0 = blockIdx.y * 32, bh = blockIdx.z;
    const int tx = threadIdx.x;
    const uint32_t* vh_hi = (const uint32_t*)g_vh_hi;
    const uint32_t* vh_lo = (const uint32_t*)g_vh_lo;
    uint32_t* vt_hi = (uint32_t*)g_vt_hi;
    uint32_t* vt_lo = (uint32_t*)g_vt_lo;

    #pragma unroll
    for (int j = 0; j < 4; j++) {
        const int idx = tx + j * 256;
        const int sl = idx >> 4, du = idx & 15;
        const size_t src = ((size_t)(bh * Ss + s0 + sl) * DK + dk0) / 2 + du;
        *(uint32_t*)&th[sl][2 * du] = vh_hi[src];
        *(uint32_t*)&tl[sl][2 * du] = vh_lo[src];
    }
    __syncthreads();
    #pragma unroll
    for (int j = 0; j < 4; j++) {
        const int idx = tx + j * 256;
        const int dkl = idx >> 5, sp = idx & 31;
        const size_t dst = (size_t)(bh * DK + dk0 + dkl) * (Ss / 2) + (s0 >> 1) + sp;
        vt_hi[dst] = (uint32_t)th[2 * sp][dkl] | ((uint32_t)th[2 * sp + 1][dkl] << 16);
        vt_lo[dst] = (uint32_t)tl[2 * sp][dkl] | ((uint32_t)tl[2 * sp + 1][dkl] << 16);
    }
}

// ===========================================================================
// scores: attn = (Q K^T)*0.125 fp32. grid (16 kt, 16 qt, 32 bh), 512 thr
// ===========================================================================
__global__ void __launch_bounds__(512) scores_mma_kernel(float* __restrict__ attn)
{
    __shared__ char sm[40960];
    const uint32_t sb = smem_u32(sm);
    const uint32_t aH = sb, aL = sb + 10240, bHs = sb + 20480, bLs = sb + 30720;

    const int bh = blockIdx.z, tx = threadIdx.x, w = tx >> 5, lane = tx & 31;
    const int kb0 = blockIdx.x * 128, q0 = blockIdx.y * 128;
    const int wm0 = (w & 3) * 32, wn0 = (w >> 2) * 32;
    const uint32_t laneOfs = (lane & 15) * STRIDE + (lane >> 4) * 16;

    const char* QH = (const char*)g_qh_hi + (size_t)bh * Ss * DK * 2;
    const char* QL = (const char*)g_qh_lo + (size_t)bh * Ss * DK * 2;
    const char* KH = (const char*)g_kh_hi + (size_t)bh * Ss * DK * 2;
    const char* KL = (const char*)g_kh_lo + (size_t)bh * Ss * DK * 2;

    float c[2][4][4] = {};

    #pragma unroll
    for (int k0 = 0; k0 < DK; k0 += 32) {
        {
            const int row = tx >> 2, cb = (tx & 3) * 16;
            const size_t qo = (size_t)(q0 + row) * (DK * 2) + k0 * 2 + cb;
            const size_t ko = (size_t)(kb0 + row) * (DK * 2) + k0 * 2 + cb;
            *(uint4*)(sm + 0     + row * STRIDE + cb) = *(const uint4*)(QH + qo);
            *(uint4*)(sm + 10240 + row * STRIDE + cb) = *(const uint4*)(QL + qo);
            *(uint4*)(sm + 20480 + row * STRIDE + cb) = *(const uint4*)(KH + ko);
            *(uint4*)(sm + 30720 + row * STRIDE + cb) = *(const uint4*)(KL + ko);
        }
        __syncthreads();
        wtile_k16<2>(c, aH, aL, bHs, bLs, wm0, wn0, 0, laneOfs);
        wtile_k16<2>(c, aH, aL, bHs, bLs, wm0, wn0, 16, laneOfs);
        __syncthreads();
    }

    const int g = lane >> 2, t2 = (lane & 3) * 2;
    #pragma unroll
    for (int mf = 0; mf < 2; mf++)
        #pragma unroll
        for (int nf = 0; nf < 4; nf++) {
            const int kc = kb0 + wn0 + nf * 8 + t2;
            #pragma unroll
            for (int rr = 0; rr < 2; rr++) {
                const int qr = q0 + wm0 + mf * 16 + g + rr * 8;
                float2 val = make_float2(c[mf][nf][2 * rr] * 0.125f,
                                         c[mf][nf][2 * rr + 1] * 0.125f);
                *(float2*)&attn[((size_t)bh * Ss + qr) * Ss + kc] = val;
            }
        }
}

// ===========================================================================
// softmax: in-place fp32, one 256-thread block per row
// ===========================================================================
__global__ void __launch_bounds__(256) softmax_kernel(float* __restrict__ attn)
{
    float* p = attn + (size_t)blockIdx.x * Ss;
    const int tx = threadIdx.x, lane = tx & 31, wid = tx >> 5;
    float v[8];
    float4 a = ((const float4*)p)[tx * 2 + 0];
    float4 b = ((const float4*)p)[tx * 2 + 1];
    v[0]=a.x; v[1]=a.y; v[2]=a.z; v[3]=a.w; v[4]=b.x; v[5]=b.y; v[6]=b.z; v[7]=b.w;
    __shared__ float red[8];
    float mx = v[0];
    #pragma unroll
    for (int i = 1; i < 8; i++) mx = fmaxf(mx, v[i]);
    #pragma unroll
    for (int o = 16; o; o >>= 1) mx = fmaxf(mx, __shfl_xor_sync(~0u, mx, o));
    if (lane == 0) red[wid] = mx;
    __syncthreads();
    mx = red[0];
    #pragma unroll
    for (int i = 1; i < 8; i++) mx = fmaxf(mx, red[i]);
    __syncthreads();
    float s = 0.f;
    #pragma unroll
    for (int i = 0; i < 8; i++) { v[i] = __expf(v[i] - mx); s += v[i]; }
    #pragma unroll
    for (int o = 16; o; o >>= 1) s += __shfl_xor_sync(~0u, s, o);
    if (lane == 0) red[wid] = s;
    __syncthreads();
    s = red[0];
    #pragma unroll
    for (int i = 1; i < 8; i++) s += red[i];
    const float inv = 1.0f / s;
    ((float4*)p)[tx * 2 + 0] = make_float4(v[0]*inv, v[1]*inv, v[2]*inv, v[3]*inv);
    ((float4*)p)[tx * 2 + 1] = make_float4(v[4]*inv, v[5]*inv, v[6]*inv, v[7]*inv);
}

// ===========================================================================
// ctx: ctx = P @ V -> bf16 hi/lo. 128x64 tile. grid (16 mt, 32 bh), 512 thr
// ===========================================================================
__global__ void __launch_bounds__(512) ctx_mma_kernel(const float* __restrict__ attn)
{
    __shared__ char sm[30720];  // AH 0, AL 10240, BH 20480, BL 25600
    const uint32_t sb = smem_u32(sm);
    const uint32_t aH = sb, aL = sb + 10240, bHs = sb + 20480, bLs = sb + 25600;

    const int bh = blockIdx.y, tx = threadIdx.x, w = tx >> 5, lane = tx & 31;
    const int m0 = blockIdx.x * 128;
    const int wm0 = (w & 3) * 32, wn0 = (w >> 2) * 16;   // 4m x 4n warps, n-tile 16
    const uint32_t laneOfs = (lane & 15) * STRIDE + (lane >> 4) * 16;

    const float* P = attn + (size_t)bh * Ss * Ss;
    const char* VTH = (const char*)g_vt_hi + (size_t)bh * DK * Ss * 2;
    const char* VTL = (const char*)g_vt_lo + (size_t)bh * DK * Ss * 2;

    float c[2][2][4] = {};

    for (int k0 = 0; k0 < Ss; k0 += 32) {
        // A: P fp32 -> split, 128x32
        #pragma unroll
        for (int j = 0; j < 2; j++) {
            const int idx = tx + j * 512;
            const int row = idx >> 3, cc = (idx & 7) * 4;
            float4 x = *(const float4*)&P[(size_t)(m0 + row) * Ss + k0 + cc];
            uint2 hi, lo;
            split4(x, hi, lo);
            *(uint2*)(sm + 0     + row * STRIDE + cc * 2) = hi;
            *(uint2*)(sm + 10240 + row * STRIDE + cc * 2) = lo;
        }
        // B: vt bf16 copy, 64 rows x 64B
        if (tx < 256) {
            const int row = tx >> 2, cb = (tx & 3) * 16;
            const size_t bo = (size_t)row * (Ss * 2) + k0 * 2 + cb;
            *(uint4*)(sm + 20480 + row * STRIDE + cb) = *(const uint4*)(VTH + bo);
            *(uint4*)(sm + 25600 + row * STRIDE + cb) = *(const uint4*)(VTL + bo);
        }
        __syncthreads();
        wtile_k16<1>(c, aH, aL, bHs, bLs, wm0, wn0, 0, laneOfs);
        wtile_k16<1>(c, aH, aL, bHs, bLs, wm0, wn0, 16, laneOfs);
        __syncthreads();
    }

    const int g = lane >> 2, t2 = (lane & 3) * 2;
    const int b = bh >> 4, h = bh & (Hh - 1);
    #pragma unroll
    for (int mf = 0; mf < 2; mf++)
        #pragma unroll
        for (int nf = 0; nf < 2; nf++) {
            const int dc = wn0 + nf * 8 + t2;
            #pragma unroll
            for (int rr = 0; rr < 2; rr++) {
                const int s = m0 + wm0 + mf * 16 + g + rr * 8;
                float f0 = c[mf][nf][2 * rr];
                float f1 = c[mf][nf][2 * rr + 1];
                uint32_t hw = pk2(f0, f1);
                float a0 = __uint_as_float(hw << 16), a1 = __uint_as_float(hw & 0xFFFF0000u);
                uint32_t lw = pk2(f0 - a0, f1 - a1);
                const size_t eo = (((size_t)(b * Ss + s)) * Dd + h * DK + dc) * 2;
                *(uint32_t*)((char*)g_ctx_hi + eo) = hw;
                *(uint32_t*)((char*)g_ctx_lo + eo) = lw;
            }
        }
}

// ===========================================================================
// out: out = ctx @ W_o + b_o fp32. grid (8 nt, 32 mt), 512 thr
// ===========================================================================
__global__ void __launch_bounds__(512) out_mma_kernel(
    const float* __restrict__ bias, float* __restrict__ out)
{
    __shared__ char sm[40960];
    const uint32_t sb = smem_u32(sm);
    const uint32_t aH = sb, aL = sb + 10240, bHs = sb + 20480, bLs = sb + 30720;

    const int tx = threadIdx.x, w = tx >> 5, lane = tx & 31;
    const int n0 = blockIdx.x * 128, m0 = blockIdx.y * 128;
    const int wm0 = (w & 3) * 32, wn0 = (w >> 2) * 32;
    const uint32_t laneOfs = (lane & 15) * STRIDE + (lane >> 4) * 16;

    const char* AH = (const char*)g_ctx_hi;
    const char* AL = (const char*)g_ctx_lo;
    const char* WtH = (const char*)g_wt_hi[3];
    const char* WtL = (const char*)g_wt_lo[3];

    float c[2][4][4] = {};

    for (int k0 = 0; k0 < Dd; k0 += 32) {
        {
            const int row = tx >> 2, cb = (tx & 3) * 16;
            const size_t ao = (size_t)(m0 + row) * (Dd * 2) + k0 * 2 + cb;
            const size_t bo = (size_t)(n0 + row) * (Dd * 2) + k0 * 2 + cb;
            *(uint4*)(sm + 0     + row * STRIDE + cb) = *(const uint4*)(AH + ao);
            *(uint4*)(sm + 10240 + row * STRIDE + cb) = *(const uint4*)(AL + ao);
            *(uint4*)(sm + 20480 + row * STRIDE + cb) = *(const uint4*)(WtH + bo);
            *(uint4*)(sm + 30720 + row * STRIDE + cb) = *(const uint4*)(WtL + bo);
        }
        __syncthreads();
        wtile_k16<2>(c, aH, aL, bHs, bLs, wm0, wn0, 0, laneOfs);
        wtile_k16<2>(c, aH, aL, bHs, bLs, wm0, wn0, 16, laneOfs);
        __syncthreads();
    }

    const int g = lane >> 2, t2 = (lane & 3) * 2;
    #pragma unroll
    for (int mf = 0; mf < 2; mf++)
        #pragma unroll
        for (int nf = 0; nf < 4; nf++) {
            const int n = n0 + wn0 + nf * 8 + t2;
            const float bf0 = bias[n], bf1 = bias[n + 1];
            #pragma unroll
            for (int rr = 0; rr < 2; rr++) {
                const int m = m0 + wm0 + mf * 16 + g + rr * 8;
                float2 val = make_float2(c[mf][nf][2 * rr] + bf0,
                                         c[mf][nf][2 * rr + 1] + bf1);
                *(float2*)&out[(size_t)m * Dd + n] = val;
            }
        }
}

// ===========================================================================
extern "C" void kernel_launch(void* const* d_in, const int* in_sizes, int n_in,
                              void* d_out, int out_size)
{
    const float* q   = (const float*)d_in[0];
    const float* k   = (const float*)d_in[1];
    const float* v   = (const float*)d_in[2];
    const float* W_q = (const float*)d_in[3];
    const float* b_q = (const float*)d_in[4];
    const float* W_k = (const float*)d_in[5];
    const float* b_k = (const float*)d_in[6];
    const float* W_v = (const float*)d_in[7];
    const float* b_v = (const float*)d_in[8];
    const float* W_o = (const float*)d_in[9];
    const float* b_o = (const float*)d_in[10];

    float* out  = (float*)d_out;
    float* attn = out + (size_t)Bb * Ss * Dd;

    prep_w_kernel<<<dim3(16, 32, 4), 256>>>(W_q, W_k, W_v, W_o);
    qkv_mma_kernel<<<dim3(8, 32, 3), 512>>>(q, k, v, b_q, b_k, b_v);
    vt_kernel<<<dim3(32, 2, 32), 256>>>();
    scores_mma_kernel<<<dim3(16, 16, 32), 512>>>(attn);
    softmax_kernel<<<BH * Ss, 256>>>(attn);
    ctx_mma_kernel<<<dim3(16, 32), 512>>>(attn);
    out_mma_kernel<<<dim3(8, 32), 512>>>(b_o, out);
}

// round 7
// speedup vs baseline: 2.2031x; 1.1318x over previous
#include <cuda_runtime.h>
#include <cuda_bf16.h>
#include <cstdint>

#define Bb 2
#define Ss 2048
#define Dd 1024
#define Hh 16
#define DK 64
#define BH (Bb*Hh)       // 32
#define MROWS (Bb*Ss)    // 4096

// ---------------- device scratch (allocation-free rule) ----------------
__device__ __nv_bfloat16 g_wt_hi[4][(size_t)Dd * Dd];   // W^T [N,K] bf16 hi
__device__ __nv_bfloat16 g_wt_lo[4][(size_t)Dd * Dd];
__device__ __nv_bfloat16 g_x_hi[3][(size_t)MROWS * Dd]; // inputs q,k,v bf16
__device__ __nv_bfloat16 g_x_lo[3][(size_t)MROWS * Dd];
__device__ __nv_bfloat16 g_qh_hi[(size_t)BH * Ss * DK]; // head-split [BH,S,dk]
__device__ __nv_bfloat16 g_qh_lo[(size_t)BH * Ss * DK];
__device__ __nv_bfloat16 g_kh_hi[(size_t)BH * Ss * DK];
__device__ __nv_bfloat16 g_kh_lo[(size_t)BH * Ss * DK];
__device__ __nv_bfloat16 g_vh_hi[(size_t)BH * Ss * DK];
__device__ __nv_bfloat16 g_vh_lo[(size_t)BH * Ss * DK];
__device__ __nv_bfloat16 g_vt_hi[(size_t)BH * DK * Ss]; // V^T [BH,dk,S]
__device__ __nv_bfloat16 g_vt_lo[(size_t)BH * DK * Ss];
__device__ __nv_bfloat16 g_sc_hi[(size_t)BH * Ss * Ss]; // exp(scores) planes
__device__ __nv_bfloat16 g_sc_lo[(size_t)BH * Ss * Ss];
__device__ __nv_bfloat16 g_ctx_hi[(size_t)MROWS * Dd];  // ctx [4096,1024]
__device__ __nv_bfloat16 g_ctx_lo[(size_t)MROWS * Dd];
__device__ float        g_rowsum[(size_t)BH * Ss];      // softmax denominators

// ---------------- helpers ----------------
__device__ __forceinline__ uint32_t smem_u32(const void* p) {
    uint32_t a;
    asm("{ .reg .u64 t; cvta.to.shared.u64 t, %1; cvt.u32.u64 %0, t; }" : "=r"(a) : "l"(p));
    return a;
}
__device__ __forceinline__ uint32_t pk2(float a, float b) {   // lo=a, hi=b
    uint32_t r;
    asm("cvt.rn.bf16x2.f32 %0, %1, %2;" : "=r"(r) : "f"(b), "f"(a));
    return r;
}
__device__ __forceinline__ void split4(float4 x, uint2& hi, uint2& lo) {
    uint32_t h0 = pk2(x.x, x.y), h1 = pk2(x.z, x.w);
    float a0 = __uint_as_float(h0 << 16), a1 = __uint_as_float(h0 & 0xFFFF0000u);
    float a2 = __uint_as_float(h1 << 16), a3 = __uint_as_float(h1 & 0xFFFF0000u);
    hi = make_uint2(h0, h1);
    lo = make_uint2(pk2(x.x - a0, x.y - a1), pk2(x.z - a2, x.w - a3));
}
__device__ __forceinline__ void ldm_x4(uint32_t (&r)[4], uint32_t addr) {
    asm volatile("ldmatrix.sync.aligned.m8n8.x4.shared.b16 {%0,%1,%2,%3}, [%4];"
        : "=r"(r[0]), "=r"(r[1]), "=r"(r[2]), "=r"(r[3]) : "r"(addr));
}
__device__ __forceinline__ void mma_bf16(float (&c)[4], const uint32_t (&a)[4],
                                         uint32_t b0, uint32_t b1) {
    asm volatile("mma.sync.aligned.m16n8k16.row.col.f32.bf16.bf16.f32 "
        "{%0,%1,%2,%3}, {%4,%5,%6,%7}, {%8,%9}, {%0,%1,%2,%3};"
        : "+f"(c[0]), "+f"(c[1]), "+f"(c[2]), "+f"(c[3])
        : "r"(a[0]), "r"(a[1]), "r"(a[2]), "r"(a[3]), "r"(b0), "r"(b1));
}
__device__ __forceinline__ void cpa16(uint32_t s, const void* g) {
    asm volatile("cp.async.cg.shared.global [%0], [%1], 16;" :: "r"(s), "l"(g));
}
#define CPA_COMMIT() asm volatile("cp.async.commit_group;" ::: "memory")
#define CPA_WAIT0()  asm volatile("cp.async.wait_group 0;" ::: "memory")
#define CPA_WAIT1()  asm volatile("cp.async.wait_group 1;" ::: "memory")

// warp tile 32x(16*NP), one k16 step; hi/lo 3-product scheme
template <int NP>
__device__ __forceinline__ void wtile_k16(
    float (&c)[2][2 * NP][4],
    uint32_t aH, uint32_t aL, uint32_t bH, uint32_t bL,
    int wm0, int wn0, int ks, uint32_t laneOfs, int stride)
{
    uint32_t ah[2][4], al[2][4], bh[NP][4], bl[NP][4];
    #pragma unroll
    for (int mf = 0; mf < 2; mf++) {
        ldm_x4(ah[mf], aH + (wm0 + mf * 16) * stride + ks * 2 + laneOfs);
        ldm_x4(al[mf], aL + (wm0 + mf * 16) * stride + ks * 2 + laneOfs);
    }
    #pragma unroll
    for (int np = 0; np < NP; np++) {
        ldm_x4(bh[np], bH + (wn0 + np * 16) * stride + ks * 2 + laneOfs);
        ldm_x4(bl[np], bL + (wn0 + np * 16) * stride + ks * 2 + laneOfs);
    }
    #pragma unroll
    for (int mf = 0; mf < 2; mf++)
        #pragma unroll
        for (int np = 0; np < NP; np++) {
            mma_bf16(c[mf][2 * np],     ah[mf], bh[np][0], bh[np][2]);
            mma_bf16(c[mf][2 * np + 1], ah[mf], bh[np][1], bh[np][3]);
            mma_bf16(c[mf][2 * np],     ah[mf], bl[np][0], bl[np][2]);
            mma_bf16(c[mf][2 * np + 1], ah[mf], bl[np][1], bl[np][3]);
            mma_bf16(c[mf][2 * np],     al[mf], bh[np][0], bh[np][2]);
            mma_bf16(c[mf][2 * np + 1], al[mf], bh[np][1], bh[np][3]);
        }
}

// ===========================================================================
// prep_w: W[K,N] fp32 -> Wt hi/lo [N,K] bf16.  grid (16, 32, 4), 256 thr
// ===========================================================================
__global__ void __launch_bounds__(256) prep_w_kernel(
    const float* __restrict__ W0, const float* __restrict__ W1,
    const float* __restrict__ W2, const float* __restrict__ W3)
{
    const float* Wz[4] = {W0, W1, W2, W3};
    const float* W = Wz[blockIdx.z];
    uint32_t* out_hi = (uint32_t*)g_wt_hi[blockIdx.z];
    uint32_t* out_lo = (uint32_t*)g_wt_lo[blockIdx.z];

    __shared__ float ts[64][33];
    const int k0 = blockIdx.x * 64, n0 = blockIdx.y * 32, tx = threadIdx.x;

    #pragma unroll
    for (int j = 0; j < 8; j++) {
        const int idx = tx + j * 256;
        const int k = idx >> 5, n = idx & 31;
        ts[k][n] = W[(size_t)(k0 + k) * Dd + n0 + n];
    }
    __syncthreads();

    #pragma unroll
    for (int j = 0; j < 4; j++) {
        const int idx = tx + j * 256;
        const int n = idx >> 5, kp = idx & 31;
        float f0 = ts[2 * kp][n], f1 = ts[2 * kp + 1][n];
        uint32_t h = pk2(f0, f1);
        float a0 = __uint_as_float(h << 16), a1 = __uint_as_float(h & 0xFFFF0000u);
        uint32_t l = pk2(f0 - a0, f1 - a1);
        const size_t o = (size_t)(n0 + n) * (Dd / 2) + (k0 >> 1) + kp;
        out_hi[o] = h;
        out_lo[o] = l;
    }
}

// ===========================================================================
// prep_x: q,k,v fp32 [4096,1024] -> bf16 hi/lo planes. grid (4096, 3), 256 thr
// ===========================================================================
__global__ void __launch_bounds__(256) prep_x_kernel(
    const float* __restrict__ q, const float* __restrict__ k, const float* __restrict__ v)
{
    const int z = blockIdx.y;
    const float* X = (z == 0) ? q : (z == 1) ? k : v;
    const int row = blockIdx.x, tx = threadIdx.x;
    float4 x = *(const float4*)&X[(size_t)row * Dd + tx * 4];
    uint2 hi, lo;
    split4(x, hi, lo);
    *(uint2*)((char*)g_x_hi[z] + (size_t)row * 2048 + tx * 8) = hi;
    *(uint2*)((char*)g_x_lo[z] + (size_t)row * 2048 + tx * 8) = lo;
}

// zero the rowsum buffer (graph-replay safe). grid (64), 256 thr
__global__ void __launch_bounds__(256) zero_rs_kernel()
{
    const int i = (blockIdx.x * 256 + threadIdx.x) * 4;
    *(float4*)&g_rowsum[i] = make_float4(0.f, 0.f, 0.f, 0.f);
}

#define STRIDE 80
#define QKV_BUF 40960   // AH 0 (10240) AL 10240 BH 20480 BL 30720

// ===========================================================================
// qkv: Y = X@W + b -> head-split bf16 hi/lo. grid (8 nt, 32 mt, 3), 512 thr
// cp.async double-buffered, dyn smem 81920.
// ===========================================================================
__global__ void __launch_bounds__(512) qkv_mma_kernel(
    const float* __restrict__ bq, const float* __restrict__ bk, const float* __restrict__ bv)
{
    extern __shared__ char sm[];
    const uint32_t sb = smem_u32(sm);

    const int z = blockIdx.z;
    const float* bias = (z == 0) ? bq : (z == 1) ? bk : bv;
    const char* XH = (const char*)g_x_hi[z];
    const char* XL = (const char*)g_x_lo[z];
    const char* WtH = (const char*)g_wt_hi[z];
    const char* WtL = (const char*)g_wt_lo[z];
    char* Y_hi = (char*)((z == 0) ? g_qh_hi : (z == 1) ? g_kh_hi : g_vh_hi);
    char* Y_lo = (char*)((z == 0) ? g_qh_lo : (z == 1) ? g_kh_lo : g_vh_lo);

    const int tx = threadIdx.x, w = tx >> 5, lane = tx & 31;
    const int n0 = blockIdx.x * 128, m0 = blockIdx.y * 128;
    const int wm0 = (w & 3) * 32, wn0 = (w >> 2) * 32;
    const uint32_t laneOfs = (lane & 15) * STRIDE + (lane >> 4) * 16;

    const int lrow = tx >> 2, lcb = (tx & 3) * 16;

    float c[2][4][4] = {};

    // prologue load k0=0 into buf 0
    {
        const uint32_t d = sb + lrow * STRIDE + lcb;
        cpa16(d + 0,     XH  + (size_t)(m0 + lrow) * 2048 + lcb);
        cpa16(d + 10240, XL  + (size_t)(m0 + lrow) * 2048 + lcb);
        cpa16(d + 20480, WtH + (size_t)(n0 + lrow) * 2048 + lcb);
        cpa16(d + 30720, WtL + (size_t)(n0 + lrow) * 2048 + lcb);
    }
    CPA_COMMIT();

    for (int it = 0; it < 32; it++) {
        if (it + 1 < 32) {
            const int k2 = (it + 1) * 64;  // byte offset along K (32 elems * 2B)
            const uint32_t d = sb + ((it + 1) & 1) * QKV_BUF + lrow * STRIDE + lcb;
            cpa16(d + 0,     XH  + (size_t)(m0 + lrow) * 2048 + k2 + lcb);
            cpa16(d + 10240, XL  + (size_t)(m0 + lrow) * 2048 + k2 + lcb);
            cpa16(d + 20480, WtH + (size_t)(n0 + lrow) * 2048 + k2 + lcb);
            cpa16(d + 30720, WtL + (size_t)(n0 + lrow) * 2048 + k2 + lcb);
            CPA_COMMIT();
            CPA_WAIT1();
        } else {
            CPA_WAIT0();
        }
        __syncthreads();
        const uint32_t cur = sb + (it & 1) * QKV_BUF;
        wtile_k16<2>(c, cur, cur + 10240, cur + 20480, cur + 30720, wm0, wn0, 0,  laneOfs, STRIDE);
        wtile_k16<2>(c, cur, cur + 10240, cur + 20480, cur + 30720, wm0, wn0, 16, laneOfs, STRIDE);
        __syncthreads();
    }

    // epilogue: bias + head-split hi/lo store
    const int g = lane >> 2, t2 = (lane & 3) * 2;
    #pragma unroll
    for (int mf = 0; mf < 2; mf++)
        #pragma unroll
        for (int nf = 0; nf < 4; nf++) {
            const int n = n0 + wn0 + nf * 8 + t2;
            const int h = n >> 6, dc = n & (DK - 1);
            const float bf0 = bias[n], bf1 = bias[n + 1];
            #pragma unroll
            for (int rr = 0; rr < 2; rr++) {
                const int m = m0 + wm0 + mf * 16 + g + rr * 8;
                const int bb = m >> 11, s = m & (Ss - 1);
                float f0 = c[mf][nf][2 * rr] + bf0;
                float f1 = c[mf][nf][2 * rr + 1] + bf1;
                uint32_t hw = pk2(f0, f1);
                float a0 = __uint_as_float(hw << 16), a1 = __uint_as_float(hw & 0xFFFF0000u);
                uint32_t lw = pk2(f0 - a0, f1 - a1);
                const size_t eo = ((((size_t)(bb * Hh + h)) * Ss + s) * DK + dc) * 2;
                *(uint32_t*)(Y_hi + eo) = hw;
                *(uint32_t*)(Y_lo + eo) = lw;
            }
        }
}

// ===========================================================================
// vt transpose: vh [bh,s,dk] -> vt [bh,dk,s]. grid (32 st, 2 dkt, 32 bh), 256 thr
// ===========================================================================
__global__ void __launch_bounds__(256) vt_kernel()
{
    __shared__ unsigned short th[64][34];
    __shared__ unsigned short tl[64][34];
    const int s0 = blockIdx.x * 64, dk0 = blockIdx.y * 32, bh = blockIdx.z;
    const int tx = threadIdx.x;
    const uint32_t* vh_hi = (const uint32_t*)g_vh_hi;
    const uint32_t* vh_lo = (const uint32_t*)g_vh_lo;
    uint32_t* vt_hi = (uint32_t*)g_vt_hi;
    uint32_t* vt_lo = (uint32_t*)g_vt_lo;

    #pragma unroll
    for (int j = 0; j < 4; j++) {
        const int idx = tx + j * 256;
        const int sl = idx >> 4, du = idx & 15;
        const size_t src = ((size_t)(bh * Ss + s0 + sl) * DK + dk0) / 2 + du;
        *(uint32_t*)&th[sl][2 * du] = vh_hi[src];
        *(uint32_t*)&tl[sl][2 * du] = vh_lo[src];
    }
    __syncthreads();
    #pragma unroll
    for (int j = 0; j < 4; j++) {
        const int idx = tx + j * 256;
        const int dkl = idx >> 5, sp = idx & 31;
        const size_t dst = (size_t)(bh * DK + dk0 + dkl) * (Ss / 2) + (s0 >> 1) + sp;
        vt_hi[dst] = (uint32_t)th[2 * sp][dkl] | ((uint32_t)th[2 * sp + 1][dkl] << 16);
        vt_lo[dst] = (uint32_t)tl[2 * sp][dkl] | ((uint32_t)tl[2 * sp + 1][dkl] << 16);
    }
}

// ===========================================================================
// scores: e = exp(QK^T * 0.125) -> bf16 hi/lo planes + row sums (atomics).
// grid (16 kt, 16 qt, 32 bh), 512 thr. dyn smem 74240. Single tile dk=64.
// planes: QH 0, QL 18432, KH 36864, KL 55296 (stride 144); rowpart @73728
// ===========================================================================
#define SC_STRIDE 144
__global__ void __launch_bounds__(512) scores_mma_kernel()
{
    extern __shared__ char sm[];
    const uint32_t sb = smem_u32(sm);
    float* rowpart = (float*)(sm + 73728);

    const int bh = blockIdx.z, tx = threadIdx.x, w = tx >> 5, lane = tx & 31;
    const int kb0 = blockIdx.x * 128, q0 = blockIdx.y * 128;
    const int wm0 = (w & 3) * 32, wn0 = (w >> 2) * 32;
    const uint32_t laneOfs = (lane & 15) * SC_STRIDE + (lane >> 4) * 16;

    const char* QH = (const char*)g_qh_hi + (size_t)bh * Ss * 128;
    const char* QL = (const char*)g_qh_lo + (size_t)bh * Ss * 128;
    const char* KH = (const char*)g_kh_hi + (size_t)bh * Ss * 128;
    const char* KL = (const char*)g_kh_lo + (size_t)bh * Ss * 128;

    if (tx < 128) rowpart[tx] = 0.f;

    // load all 4 planes (128 rows x 128B each)
    #pragma unroll
    for (int j = 0; j < 2; j++) {
        const int idx = tx + j * 512;
        const int row = idx >> 3, cb = (idx & 7) * 16;
        const uint32_t d = sb + row * SC_STRIDE + cb;
        cpa16(d + 0,     QH + (size_t)(q0 + row) * 128 + cb);
        cpa16(d + 18432, QL + (size_t)(q0 + row) * 128 + cb);
        cpa16(d + 36864, KH + (size_t)(kb0 + row) * 128 + cb);
        cpa16(d + 55296, KL + (size_t)(kb0 + row) * 128 + cb);
    }
    CPA_COMMIT();
    CPA_WAIT0();
    __syncthreads();

    float c[2][4][4] = {};
    wtile_k16<2>(c, sb, sb + 18432, sb + 36864, sb + 55296, wm0, wn0, 0,  laneOfs, SC_STRIDE);
    wtile_k16<2>(c, sb, sb + 18432, sb + 36864, sb + 55296, wm0, wn0, 16, laneOfs, SC_STRIDE);
    wtile_k16<2>(c, sb, sb + 18432, sb + 36864, sb + 55296, wm0, wn0, 32, laneOfs, SC_STRIDE);
    wtile_k16<2>(c, sb, sb + 18432, sb + 36864, sb + 55296, wm0, wn0, 48, laneOfs, SC_STRIDE);

    // epilogue: exp, store bf16 hi/lo planes, accumulate row sums
    const int g = lane >> 2, t2 = (lane & 3) * 2;
    char* SH = (char*)g_sc_hi;
    char* SL = (char*)g_sc_lo;
    float part[2][2] = {};
    #pragma unroll
    for (int mf = 0; mf < 2; mf++)
        #pragma unroll
        for (int nf = 0; nf < 4; nf++) {
            const int kc = kb0 + wn0 + nf * 8 + t2;
            #pragma unroll
            for (int rr = 0; rr < 2; rr++) {
                const int qr = q0 + wm0 + mf * 16 + g + rr * 8;
                float e0 = __expf(c[mf][nf][2 * rr] * 0.125f);
                float e1 = __expf(c[mf][nf][2 * rr + 1] * 0.125f);
                part[mf][rr] += e0 + e1;
                uint32_t hw = pk2(e0, e1);
                float a0 = __uint_as_float(hw << 16), a1 = __uint_as_float(hw & 0xFFFF0000u);
                uint32_t lw = pk2(e0 - a0, e1 - a1);
                const size_t eo = (((size_t)bh * Ss + qr) * Ss + kc) * 2;
                *(uint32_t*)(SH + eo) = hw;
                *(uint32_t*)(SL + eo) = lw;
            }
        }
    #pragma unroll
    for (int mf = 0; mf < 2; mf++)
        #pragma unroll
        for (int rr = 0; rr < 2; rr++) {
            float p = part[mf][rr];
            p += __shfl_xor_sync(~0u, p, 1);
            p += __shfl_xor_sync(~0u, p, 2);
            if ((lane & 3) == 0)
                atomicAdd(&rowpart[wm0 + mf * 16 + rr * 8 + g], p);
        }
    __syncthreads();
    if (tx < 128)
        atomicAdd(&g_rowsum[(size_t)bh * Ss + q0 + tx], rowpart[tx]);
}

// ===========================================================================
// ctx: C = (P@V)/s -> bf16 hi/lo; also writes normalized attn fp32.
// tile 256m x 64n, 16 warps (8m x 2n). grid (8 mt, 32 bh), 512 thr.
// dyn smem 103424: buf 51200 x2 (AH 0 (20480) AL 20480 BH 40960 (5120) BL 46080),
// inv_s @102400 (256 floats)
// ===========================================================================
#define CTX_BUF 51200
__global__ void __launch_bounds__(512) ctx_mma_kernel(float* __restrict__ attn)
{
    extern __shared__ char sm[];
    const uint32_t sb = smem_u32(sm);
    float* inv_s = (float*)(sm + 102400);

    const int bh = blockIdx.y, tx = threadIdx.x, w = tx >> 5, lane = tx & 31;
    const int m0 = blockIdx.x * 256;
    const int wm0 = (w & 7) * 32, wn0 = (w >> 3) * 32;
    const uint32_t laneOfs = (lane & 15) * STRIDE + (lane >> 4) * 16;

    const char* SH = (const char*)g_sc_hi + (size_t)bh * Ss * 4096;
    const char* SL = (const char*)g_sc_lo + (size_t)bh * Ss * 4096;
    const char* VTH = (const char*)g_vt_hi + (size_t)bh * DK * 4096;
    const char* VTL = (const char*)g_vt_lo + (size_t)bh * DK * 4096;

    if (tx < 256) inv_s[tx] = 1.0f / g_rowsum[(size_t)bh * Ss + m0 + tx];

    const int arow = tx >> 1, acb = (tx & 1) * 32;       // A: 256 rows x 2 chunks32
    const int bpl = tx >> 8, brow = (tx & 255) >> 2, bcb = (tx & 3) * 16;

    // prologue
    {
        const uint32_t da = sb + arow * STRIDE + acb;
        cpa16(da + 0,      SH + (size_t)(m0 + arow) * 4096 + acb);
        cpa16(da + 16,     SH + (size_t)(m0 + arow) * 4096 + acb + 16);
        cpa16(da + 20480,      SL + (size_t)(m0 + arow) * 4096 + acb);
        cpa16(da + 20480 + 16, SL + (size_t)(m0 + arow) * 4096 + acb + 16);
        const uint32_t db = sb + 40960 + bpl * 5120 + brow * STRIDE + bcb;
        cpa16(db, (bpl ? VTL : VTH) + (size_t)brow * 4096 + bcb);
    }
    CPA_COMMIT();

    float c[2][4][4] = {};

    for (int it = 0; it < 64; it++) {
        if (it + 1 < 64) {
            const int k2 = (it + 1) * 64;
            const uint32_t bufb = sb + ((it + 1) & 1) * CTX_BUF;
            const uint32_t da = bufb + arow * STRIDE + acb;
            cpa16(da + 0,      SH + (size_t)(m0 + arow) * 4096 + k2 + acb);
            cpa16(da + 16,     SH + (size_t)(m0 + arow) * 4096 + k2 + acb + 16);
            cpa16(da + 20480,      SL + (size_t)(m0 + arow) * 4096 + k2 + acb);
            cpa16(da + 20480 + 16, SL + (size_t)(m0 + arow) * 4096 + k2 + acb + 16);
            const uint32_t db = bufb + 40960 + bpl * 5120 + brow * STRIDE + bcb;
            cpa16(db, (bpl ? VTL : VTH) + (size_t)brow * 4096 + k2 + bcb);
            CPA_COMMIT();
            CPA_WAIT1();
        } else {
            CPA_WAIT0();
        }
        __syncthreads();
        const uint32_t cur = sb + (it & 1) * CTX_BUF;
        const int k0 = it * 32;

        // write normalized attn for this 256x32 block from smem
        #pragma unroll
        for (int j = 0; j < 4; j++) {
            const int idx = tx + j * 512;
            const int row = idx >> 3, c4 = (idx & 7) * 4;
            uint2 hv = *(uint2*)(sm + (it & 1) * CTX_BUF + row * STRIDE + c4 * 2);
            uint2 lv = *(uint2*)(sm + (it & 1) * CTX_BUF + 20480 + row * STRIDE + c4 * 2);
            const float is = inv_s[row];
            float4 o;
            o.x = (__uint_as_float(hv.x << 16)        + __uint_as_float(lv.x << 16)) * is;
            o.y = (__uint_as_float(hv.x & 0xFFFF0000u) + __uint_as_float(lv.x & 0xFFFF0000u)) * is;
            o.z = (__uint_as_float(hv.y << 16)        + __uint_as_float(lv.y << 16)) * is;
            o.w = (__uint_as_float(hv.y & 0xFFFF0000u) + __uint_as_float(lv.y & 0xFFFF0000u)) * is;
            *(float4*)&attn[((size_t)bh * Ss + m0 + row) * Ss + k0 + c4] = o;
        }

        wtile_k16<2>(c, cur, cur + 20480, cur + 40960, cur + 46080, wm0, wn0, 0,  laneOfs, STRIDE);
        wtile_k16<2>(c, cur, cur + 20480, cur + 40960, cur + 46080, wm0, wn0, 16, laneOfs, STRIDE);
        __syncthreads();
    }

    // epilogue: scale by inv_s, split, store ctx planes
    const int g = lane >> 2, t2 = (lane & 3) * 2;
    const int b = bh >> 4, h = bh & (Hh - 1);
    #pragma unroll
    for (int mf = 0; mf < 2; mf++)
        #pragma unroll
        for (int nf = 0; nf < 4; nf++) {
            const int dc = wn0 + nf * 8 + t2;
            #pragma unroll
            for (int rr = 0; rr < 2; rr++) {
                const int sl = wm0 + mf * 16 + g + rr * 8;   // local row
                const float is = inv_s[sl];
                float f0 = c[mf][nf][2 * rr] * is;
                float f1 = c[mf][nf][2 * rr + 1] * is;
                uint32_t hw = pk2(f0, f1);
                float a0 = __uint_as_float(hw << 16), a1 = __uint_as_float(hw & 0xFFFF0000u);
                uint32_t lw = pk2(f0 - a0, f1 - a1);
                const size_t eo = (((size_t)(b * Ss + m0 + sl)) * Dd + h * DK + dc) * 2;
                *(uint32_t*)((char*)g_ctx_hi + eo) = hw;
                *(uint32_t*)((char*)g_ctx_lo + eo) = lw;
            }
        }
}

// ===========================================================================
// out: out = ctx @ W_o + b_o fp32. grid (8 nt, 32 mt), 512 thr, dyn smem 81920
// ===========================================================================
__global__ void __launch_bounds__(512) out_mma_kernel(
    const float* __restrict__ bias, float* __restrict__ out)
{
    extern __shared__ char sm[];
    const uint32_t sb = smem_u32(sm);

    const int tx = threadIdx.x, w = tx >> 5, lane = tx & 31;
    const int n0 = blockIdx.x * 128, m0 = blockIdx.y * 128;
    const int wm0 = (w & 3) * 32, wn0 = (w >> 2) * 32;
    const uint32_t laneOfs = (lane & 15) * STRIDE + (lane >> 4) * 16;

    const char* AH = (const char*)g_ctx_hi;
    const char* AL = (const char*)g_ctx_lo;
    const char* WtH = (const char*)g_wt_hi[3];
    const char* WtL = (const char*)g_wt_lo[3];

    const int lrow = tx >> 2, lcb = (tx & 3) * 16;

    float c[2][4][4] = {};

    {
        const uint32_t d = sb + lrow * STRIDE + lcb;
        cpa16(d + 0,     AH  + (size_t)(m0 + lrow) * 2048 + lcb);
        cpa16(d + 10240, AL  + (size_t)(m0 + lrow) * 2048 + lcb);
        cpa16(d + 20480, WtH + (size_t)(n0 + lrow) * 2048 + lcb);
        cpa16(d + 30720, WtL + (size_t)(n0 + lrow) * 2048 + lcb);
    }
    CPA_COMMIT();

    for (int it = 0; it < 32; it++) {
        if (it + 1 < 32) {
            const int k2 = (it + 1) * 64;
            const uint32_t d = sb + ((it + 1) & 1) * QKV_BUF + lrow * STRIDE + lcb;
            cpa16(d + 0,     AH  + (size_t)(m0 + lrow) * 2048 + k2 + lcb);
            cpa16(d + 10240, AL  + (size_t)(m0 + lrow) * 2048 + k2 + lcb);
            cpa16(d + 20480, WtH + (size_t)(n0 + lrow) * 2048 + k2 + lcb);
            cpa16(d + 30720, WtL + (size_t)(n0 + lrow) * 2048 + k2 + lcb);
            CPA_COMMIT();
            CPA_WAIT1();
        } else {
            CPA_WAIT0();
        }
        __syncthreads();
        const uint32_t cur = sb + (it & 1) * QKV_BUF;
        wtile_k16<2>(c, cur, cur + 10240, cur + 20480, cur + 30720, wm0, wn0, 0,  laneOfs, STRIDE);
        wtile_k16<2>(c, cur, cur + 10240, cur + 20480, cur + 30720, wm0, wn0, 16, laneOfs, STRIDE);
        __syncthreads();
    }

    const int g = lane >> 2, t2 = (lane & 3) * 2;
    #pragma unroll
    for (int mf = 0; mf < 2; mf++)
        #pragma unroll
        for (int nf = 0; nf < 4; nf++) {
            const int n = n0 + wn0 + nf * 8 + t2;
            const float bf0 = bias[n], bf1 = bias[n + 1];
            #pragma unroll
            for (int rr = 0; rr < 2; rr++) {
                const int m = m0 + wm0 + mf * 16 + g + rr * 8;
                float2 val = make_float2(c[mf][nf][2 * rr] + bf0,
                                         c[mf][nf][2 * rr + 1] + bf1);
                *(float2*)&out[(size_t)m * Dd + n] = val;
            }
        }
}

// ===========================================================================
extern "C" void kernel_launch(void* const* d_in, const int* in_sizes, int n_in,
                              void* d_out, int out_size)
{
    const float* q   = (const float*)d_in[0];
    const float* k   = (const float*)d_in[1];
    const float* v   = (const float*)d_in[2];
    const float* W_q = (const float*)d_in[3];
    const float* b_q = (const float*)d_in[4];
    const float* W_k = (const float*)d_in[5];
    const float* b_k = (const float*)d_in[6];
    const float* W_v = (const float*)d_in[7];
    const float* b_v = (const float*)d_in[8];
    const float* W_o = (const float*)d_in[9];
    const float* b_o = (const float*)d_in[10];

    float* out  = (float*)d_out;
    float* attn = out + (size_t)Bb * Ss * Dd;

    static int smem_set = 0;
    if (!smem_set) {
        cudaFuncSetAttribute(qkv_mma_kernel,    cudaFuncAttributeMaxDynamicSharedMemorySize, 81920);
        cudaFuncSetAttribute(scores_mma_kernel, cudaFuncAttributeMaxDynamicSharedMemorySize, 74240);
        cudaFuncSetAttribute(ctx_mma_kernel,    cudaFuncAttributeMaxDynamicSharedMemorySize, 103424);
        cudaFuncSetAttribute(out_mma_kernel,    cudaFuncAttributeMaxDynamicSharedMemorySize, 81920);
        smem_set = 1;
    }

    prep_w_kernel<<<dim3(16, 32, 4), 256>>>(W_q, W_k, W_v, W_o);
    prep_x_kernel<<<dim3(4096, 3), 256>>>(q, k, v);
    zero_rs_kernel<<<64, 256>>>();
    qkv_mma_kernel<<<dim3(8, 32, 3), 512, 81920>>>(b_q, b_k, b_v);
    vt_kernel<<<dim3(32, 2, 32), 256>>>();
    scores_mma_kernel<<<dim3(16, 16, 32), 512, 74240>>>();
    ctx_mma_kernel<<<dim3(8, 32), 512, 103424>>>(attn);
    out_mma_kernel<<<dim3(8, 32), 512, 81920>>>(b_o, out);
}

// round 8
// speedup vs baseline: 2.2285x; 1.0116x over previous
#include <cuda_runtime.h>
#include <cuda_bf16.h>
#include <cstdint>

#define Bb 2
#define Ss 2048
#define Dd 1024
#define Hh 16
#define DK 64
#define BH (Bb*Hh)       // 32
#define MROWS (Bb*Ss)    // 4096

// ---------------- device scratch (allocation-free rule) ----------------
__device__ __nv_bfloat16 g_wt_hi[4][(size_t)Dd * Dd];   // W^T [N,K] bf16 hi
__device__ __nv_bfloat16 g_wt_lo[4][(size_t)Dd * Dd];
__device__ __nv_bfloat16 g_x_hi[3][(size_t)MROWS * Dd]; // inputs q,k,v bf16
__device__ __nv_bfloat16 g_x_lo[3][(size_t)MROWS * Dd];
__device__ __nv_bfloat16 g_qh_hi[(size_t)BH * Ss * DK]; // head-split [BH,S,dk]
__device__ __nv_bfloat16 g_qh_lo[(size_t)BH * Ss * DK];
__device__ __nv_bfloat16 g_kh_hi[(size_t)BH * Ss * DK];
__device__ __nv_bfloat16 g_kh_lo[(size_t)BH * Ss * DK];
__device__ __nv_bfloat16 g_vh_hi[(size_t)BH * Ss * DK];
__device__ __nv_bfloat16 g_vh_lo[(size_t)BH * Ss * DK];
__device__ __nv_bfloat16 g_vt_hi[(size_t)BH * DK * Ss]; // V^T [BH,dk,S]
__device__ __nv_bfloat16 g_vt_lo[(size_t)BH * DK * Ss];
__device__ __nv_bfloat16 g_sc_hi[(size_t)BH * Ss * Ss]; // exp(scores) planes
__device__ __nv_bfloat16 g_sc_lo[(size_t)BH * Ss * Ss];
__device__ __nv_bfloat16 g_ctx_hi[(size_t)MROWS * Dd];  // ctx [4096,1024]
__device__ __nv_bfloat16 g_ctx_lo[(size_t)MROWS * Dd];
__device__ float        g_rowsum[(size_t)BH * Ss];      // softmax denominators

// ---------------- helpers ----------------
__device__ __forceinline__ uint32_t smem_u32(const void* p) {
    uint32_t a;
    asm("{ .reg .u64 t; cvta.to.shared.u64 t, %1; cvt.u32.u64 %0, t; }" : "=r"(a) : "l"(p));
    return a;
}
__device__ __forceinline__ uint32_t pk2(float a, float b) {   // lo=a, hi=b
    uint32_t r;
    asm("cvt.rn.bf16x2.f32 %0, %1, %2;" : "=r"(r) : "f"(b), "f"(a));
    return r;
}
__device__ __forceinline__ void split4(float4 x, uint2& hi, uint2& lo) {
    uint32_t h0 = pk2(x.x, x.y), h1 = pk2(x.z, x.w);
    float a0 = __uint_as_float(h0 << 16), a1 = __uint_as_float(h0 & 0xFFFF0000u);
    float a2 = __uint_as_float(h1 << 16), a3 = __uint_as_float(h1 & 0xFFFF0000u);
    hi = make_uint2(h0, h1);
    lo = make_uint2(pk2(x.x - a0, x.y - a1), pk2(x.z - a2, x.w - a3));
}
__device__ __forceinline__ void ldm_x4(uint32_t (&r)[4], uint32_t addr) {
    asm volatile("ldmatrix.sync.aligned.m8n8.x4.shared.b16 {%0,%1,%2,%3}, [%4];"
        : "=r"(r[0]), "=r"(r[1]), "=r"(r[2]), "=r"(r[3]) : "r"(addr));
}
__device__ __forceinline__ void mma_bf16(float (&c)[4], const uint32_t (&a)[4],
                                         uint32_t b0, uint32_t b1) {
    asm volatile("mma.sync.aligned.m16n8k16.row.col.f32.bf16.bf16.f32 "
        "{%0,%1,%2,%3}, {%4,%5,%6,%7}, {%8,%9}, {%0,%1,%2,%3};"
        : "+f"(c[0]), "+f"(c[1]), "+f"(c[2]), "+f"(c[3])
        : "r"(a[0]), "r"(a[1]), "r"(a[2]), "r"(a[3]), "r"(b0), "r"(b1));
}
__device__ __forceinline__ void cpa16(uint32_t s, const void* g) {
    asm volatile("cp.async.cg.shared.global [%0], [%1], 16;" :: "r"(s), "l"(g));
}
#define CPA_COMMIT() asm volatile("cp.async.commit_group;" ::: "memory")
#define CPA_WAIT0()  asm volatile("cp.async.wait_group 0;" ::: "memory")
#define CPA_WAIT1()  asm volatile("cp.async.wait_group 1;" ::: "memory")

// warp tile 32x(16*NP), one k16 step; hi/lo 3-product scheme
template <int NP>
__device__ __forceinline__ void wtile_k16(
    float (&c)[2][2 * NP][4],
    uint32_t aH, uint32_t aL, uint32_t bH, uint32_t bL,
    int wm0, int wn0, int ks, uint32_t laneOfs, int stride)
{
    uint32_t ah[2][4], al[2][4], bh[NP][4], bl[NP][4];
    #pragma unroll
    for (int mf = 0; mf < 2; mf++) {
        ldm_x4(ah[mf], aH + (wm0 + mf * 16) * stride + ks * 2 + laneOfs);
        ldm_x4(al[mf], aL + (wm0 + mf * 16) * stride + ks * 2 + laneOfs);
    }
    #pragma unroll
    for (int np = 0; np < NP; np++) {
        ldm_x4(bh[np], bH + (wn0 + np * 16) * stride + ks * 2 + laneOfs);
        ldm_x4(bl[np], bL + (wn0 + np * 16) * stride + ks * 2 + laneOfs);
    }
    #pragma unroll
    for (int mf = 0; mf < 2; mf++)
        #pragma unroll
        for (int np = 0; np < NP; np++) {
            mma_bf16(c[mf][2 * np],     ah[mf], bh[np][0], bh[np][2]);
            mma_bf16(c[mf][2 * np + 1], ah[mf], bh[np][1], bh[np][3]);
            mma_bf16(c[mf][2 * np],     ah[mf], bl[np][0], bl[np][2]);
            mma_bf16(c[mf][2 * np + 1], ah[mf], bl[np][1], bl[np][3]);
            mma_bf16(c[mf][2 * np],     al[mf], bh[np][0], bh[np][2]);
            mma_bf16(c[mf][2 * np + 1], al[mf], bh[np][1], bh[np][3]);
        }
}

// ===========================================================================
// prep_w: W[K,N] fp32 -> Wt hi/lo [N,K] bf16.  grid (16, 32, 4), 256 thr
// ===========================================================================
__global__ void __launch_bounds__(256) prep_w_kernel(
    const float* __restrict__ W0, const float* __restrict__ W1,
    const float* __restrict__ W2, const float* __restrict__ W3)
{
    const float* Wz[4] = {W0, W1, W2, W3};
    const float* W = Wz[blockIdx.z];
    uint32_t* out_hi = (uint32_t*)g_wt_hi[blockIdx.z];
    uint32_t* out_lo = (uint32_t*)g_wt_lo[blockIdx.z];

    __shared__ float ts[64][33];
    const int k0 = blockIdx.x * 64, n0 = blockIdx.y * 32, tx = threadIdx.x;

    #pragma unroll
    for (int j = 0; j < 8; j++) {
        const int idx = tx + j * 256;
        const int k = idx >> 5, n = idx & 31;
        ts[k][n] = W[(size_t)(k0 + k) * Dd + n0 + n];
    }
    __syncthreads();

    #pragma unroll
    for (int j = 0; j < 4; j++) {
        const int idx = tx + j * 256;
        const int n = idx >> 5, kp = idx & 31;
        float f0 = ts[2 * kp][n], f1 = ts[2 * kp + 1][n];
        uint32_t h = pk2(f0, f1);
        float a0 = __uint_as_float(h << 16), a1 = __uint_as_float(h & 0xFFFF0000u);
        uint32_t l = pk2(f0 - a0, f1 - a1);
        const size_t o = (size_t)(n0 + n) * (Dd / 2) + (k0 >> 1) + kp;
        out_hi[o] = h;
        out_lo[o] = l;
    }
}

// ===========================================================================
// prep_x: q,k,v fp32 [4096,1024] -> bf16 hi/lo planes. grid (4096, 3), 256 thr
// ===========================================================================
__global__ void __launch_bounds__(256) prep_x_kernel(
    const float* __restrict__ q, const float* __restrict__ k, const float* __restrict__ v)
{
    const int z = blockIdx.y;
    const float* X = (z == 0) ? q : (z == 1) ? k : v;
    const int row = blockIdx.x, tx = threadIdx.x;
    float4 x = *(const float4*)&X[(size_t)row * Dd + tx * 4];
    uint2 hi, lo;
    split4(x, hi, lo);
    *(uint2*)((char*)g_x_hi[z] + (size_t)row * 2048 + tx * 8) = hi;
    *(uint2*)((char*)g_x_lo[z] + (size_t)row * 2048 + tx * 8) = lo;
}

// zero the rowsum buffer (graph-replay safe). grid (64), 256 thr
__global__ void __launch_bounds__(256) zero_rs_kernel()
{
    const int i = (blockIdx.x * 256 + threadIdx.x) * 4;
    *(float4*)&g_rowsum[i] = make_float4(0.f, 0.f, 0.f, 0.f);
}

#define STRIDE 80
#define QKV_BUF 40960   // per stage: AH 0 (10240) AL 10240 BH 20480 BL 30720

// ===========================================================================
// qkv: Y = X@W + b -> head-split bf16 hi/lo. grid (8 nt, 32 mt, 3), 512 thr
// 3-stage cp.async pipeline, ONE sync per iter. dyn smem 122880.
// ===========================================================================
__global__ void __launch_bounds__(512) qkv_mma_kernel(
    const float* __restrict__ bq, const float* __restrict__ bk, const float* __restrict__ bv)
{
    extern __shared__ char sm[];
    const uint32_t sb = smem_u32(sm);

    const int z = blockIdx.z;
    const float* bias = (z == 0) ? bq : (z == 1) ? bk : bv;
    const char* XH = (const char*)g_x_hi[z];
    const char* XL = (const char*)g_x_lo[z];
    const char* WtH = (const char*)g_wt_hi[z];
    const char* WtL = (const char*)g_wt_lo[z];
    char* Y_hi = (char*)((z == 0) ? g_qh_hi : (z == 1) ? g_kh_hi : g_vh_hi);
    char* Y_lo = (char*)((z == 0) ? g_qh_lo : (z == 1) ? g_kh_lo : g_vh_lo);

    const int tx = threadIdx.x, w = tx >> 5, lane = tx & 31;
    const int n0 = blockIdx.x * 128, m0 = blockIdx.y * 128;
    const int wm0 = (w & 3) * 32, wn0 = (w >> 2) * 32;
    const uint32_t laneOfs = (lane & 15) * STRIDE + (lane >> 4) * 16;

    const int lrow = tx >> 2, lcb = (tx & 3) * 16;
    const size_t gxr = (size_t)(m0 + lrow) * 2048 + lcb;
    const size_t gwr = (size_t)(n0 + lrow) * 2048 + lcb;
    const uint32_t dst = sb + lrow * STRIDE + lcb;

    float c[2][4][4] = {};

    #pragma unroll
    for (int p = 0; p < 2; p++) {
        const uint32_t d = dst + p * QKV_BUF;
        cpa16(d + 0,     XH  + gxr + p * 64);
        cpa16(d + 10240, XL  + gxr + p * 64);
        cpa16(d + 20480, WtH + gwr + p * 64);
        cpa16(d + 30720, WtL + gwr + p * 64);
        CPA_COMMIT();
    }

    for (int it = 0; it < 32; it++) {
        if (it == 31) { CPA_WAIT0(); } else { CPA_WAIT1(); }
        __syncthreads();
        if (it + 2 < 32) {
            const uint32_t d = dst + ((it + 2) % 3) * QKV_BUF;
            const int k2 = (it + 2) * 64;
            cpa16(d + 0,     XH  + gxr + k2);
            cpa16(d + 10240, XL  + gxr + k2);
            cpa16(d + 20480, WtH + gwr + k2);
            cpa16(d + 30720, WtL + gwr + k2);
            CPA_COMMIT();
        }
        const uint32_t cur = sb + (it % 3) * QKV_BUF;
        wtile_k16<2>(c, cur, cur + 10240, cur + 20480, cur + 30720, wm0, wn0, 0,  laneOfs, STRIDE);
        wtile_k16<2>(c, cur, cur + 10240, cur + 20480, cur + 30720, wm0, wn0, 16, laneOfs, STRIDE);
    }

    // epilogue: bias + head-split hi/lo store
    const int g = lane >> 2, t2 = (lane & 3) * 2;
    #pragma unroll
    for (int mf = 0; mf < 2; mf++)
        #pragma unroll
        for (int nf = 0; nf < 4; nf++) {
            const int n = n0 + wn0 + nf * 8 + t2;
            const int h = n >> 6, dc = n & (DK - 1);
            const float bf0 = bias[n], bf1 = bias[n + 1];
            #pragma unroll
            for (int rr = 0; rr < 2; rr++) {
                const int m = m0 + wm0 + mf * 16 + g + rr * 8;
                const int bb = m >> 11, s = m & (Ss - 1);
                float f0 = c[mf][nf][2 * rr] + bf0;
                float f1 = c[mf][nf][2 * rr + 1] + bf1;
                uint32_t hw = pk2(f0, f1);
                float a0 = __uint_as_float(hw << 16), a1 = __uint_as_float(hw & 0xFFFF0000u);
                uint32_t lw = pk2(f0 - a0, f1 - a1);
                const size_t eo = ((((size_t)(bb * Hh + h)) * Ss + s) * DK + dc) * 2;
                *(uint32_t*)(Y_hi + eo) = hw;
                *(uint32_t*)(Y_lo + eo) = lw;
            }
        }
}

// ===========================================================================
// vt transpose: vh [bh,s,dk] -> vt [bh,dk,s]. grid (32 st, 2 dkt, 32 bh), 256 thr
// ===========================================================================
__global__ void __launch_bounds__(256) vt_kernel()
{
    __shared__ unsigned short th[64][34];
    __shared__ unsigned short tl[64][34];
    const int s0 = blockIdx.x * 64, dk0 = blockIdx.y * 32, bh = blockIdx.z;
    const int tx = threadIdx.x;
    const uint32_t* vh_hi = (const uint32_t*)g_vh_hi;
    const uint32_t* vh_lo = (const uint32_t*)g_vh_lo;
    uint32_t* vt_hi = (uint32_t*)g_vt_hi;
    uint32_t* vt_lo = (uint32_t*)g_vt_lo;

    #pragma unroll
    for (int j = 0; j < 4; j++) {
        const int idx = tx + j * 256;
        const int sl = idx >> 4, du = idx & 15;
        const size_t src = ((size_t)(bh * Ss + s0 + sl) * DK + dk0) / 2 + du;
        *(uint32_t*)&th[sl][2 * du] = vh_hi[src];
        *(uint32_t*)&tl[sl][2 * du] = vh_lo[src];
    }
    __syncthreads();
    #pragma unroll
    for (int j = 0; j < 4; j++) {
        const int idx = tx + j * 256;
        const int dkl = idx >> 5, sp = idx & 31;
        const size_t dst = (size_t)(bh * DK + dk0 + dkl) * (Ss / 2) + (s0 >> 1) + sp;
        vt_hi[dst] = (uint32_t)th[2 * sp][dkl] | ((uint32_t)th[2 * sp + 1][dkl] << 16);
        vt_lo[dst] = (uint32_t)tl[2 * sp][dkl] | ((uint32_t)tl[2 * sp + 1][dkl] << 16);
    }
}

// ===========================================================================
// scores: e = exp(QK^T * 0.125) -> bf16 hi/lo planes + row sums (atomics).
// grid (16 kt, 16 qt, 32 bh), 512 thr. dyn smem 74240. Single tile dk=64.
// planes: QH 0, QL 18432, KH 36864, KL 55296 (stride 144); rowpart @73728
// ===========================================================================
#define SC_STRIDE 144
__global__ void __launch_bounds__(512) scores_mma_kernel()
{
    extern __shared__ char sm[];
    const uint32_t sb = smem_u32(sm);
    float* rowpart = (float*)(sm + 73728);

    const int bh = blockIdx.z, tx = threadIdx.x, w = tx >> 5, lane = tx & 31;
    const int kb0 = blockIdx.x * 128, q0 = blockIdx.y * 128;
    const int wm0 = (w & 3) * 32, wn0 = (w >> 2) * 32;
    const uint32_t laneOfs = (lane & 15) * SC_STRIDE + (lane >> 4) * 16;

    const char* QH = (const char*)g_qh_hi + (size_t)bh * Ss * 128;
    const char* QL = (const char*)g_qh_lo + (size_t)bh * Ss * 128;
    const char* KH = (const char*)g_kh_hi + (size_t)bh * Ss * 128;
    const char* KL = (const char*)g_kh_lo + (size_t)bh * Ss * 128;

    if (tx < 128) rowpart[tx] = 0.f;

    // load all 4 planes (128 rows x 128B each)
    #pragma unroll
    for (int j = 0; j < 2; j++) {
        const int idx = tx + j * 512;
        const int row = idx >> 3, cb = (idx & 7) * 16;
        const uint32_t d = sb + row * SC_STRIDE + cb;
        cpa16(d + 0,     QH + (size_t)(q0 + row) * 128 + cb);
        cpa16(d + 18432, QL + (size_t)(q0 + row) * 128 + cb);
        cpa16(d + 36864, KH + (size_t)(kb0 + row) * 128 + cb);
        cpa16(d + 55296, KL + (size_t)(kb0 + row) * 128 + cb);
    }
    CPA_COMMIT();
    CPA_WAIT0();
    __syncthreads();

    float c[2][4][4] = {};
    wtile_k16<2>(c, sb, sb + 18432, sb + 36864, sb + 55296, wm0, wn0, 0,  laneOfs, SC_STRIDE);
    wtile_k16<2>(c, sb, sb + 18432, sb + 36864, sb + 55296, wm0, wn0, 16, laneOfs, SC_STRIDE);
    wtile_k16<2>(c, sb, sb + 18432, sb + 36864, sb + 55296, wm0, wn0, 32, laneOfs, SC_STRIDE);
    wtile_k16<2>(c, sb, sb + 18432, sb + 36864, sb + 55296, wm0, wn0, 48, laneOfs, SC_STRIDE);

    // epilogue: exp, store bf16 hi/lo planes, accumulate row sums
    const int g = lane >> 2, t2 = (lane & 3) * 2;
    char* SH = (char*)g_sc_hi;
    char* SL = (char*)g_sc_lo;
    float part[2][2] = {};
    #pragma unroll
    for (int mf = 0; mf < 2; mf++)
        #pragma unroll
        for (int nf = 0; nf < 4; nf++) {
            const int kc = kb0 + wn0 + nf * 8 + t2;
            #pragma unroll
            for (int rr = 0; rr < 2; rr++) {
                const int qr = q0 + wm0 + mf * 16 + g + rr * 8;
                float e0 = __expf(c[mf][nf][2 * rr] * 0.125f);
                float e1 = __expf(c[mf][nf][2 * rr + 1] * 0.125f);
                part[mf][rr] += e0 + e1;
                uint32_t hw = pk2(e0, e1);
                float a0 = __uint_as_float(hw << 16), a1 = __uint_as_float(hw & 0xFFFF0000u);
                uint32_t lw = pk2(e0 - a0, e1 - a1);
                const size_t eo = (((size_t)bh * Ss + qr) * Ss + kc) * 2;
                *(uint32_t*)(SH + eo) = hw;
                *(uint32_t*)(SL + eo) = lw;
            }
        }
    #pragma unroll
    for (int mf = 0; mf < 2; mf++)
        #pragma unroll
        for (int rr = 0; rr < 2; rr++) {
            float p = part[mf][rr];
            p += __shfl_xor_sync(~0u, p, 1);
            p += __shfl_xor_sync(~0u, p, 2);
            if ((lane & 3) == 0)
                atomicAdd(&rowpart[wm0 + mf * 16 + rr * 8 + g], p);
        }
    __syncthreads();
    if (tx < 128)
        atomicAdd(&g_rowsum[(size_t)bh * Ss + q0 + tx], rowpart[tx]);
}

// ===========================================================================
// ctx: C = (P@V)/s -> bf16 hi/lo; also writes normalized attn fp32.
// tile 256m x 64n, 16 warps (8m x 2n). grid (8 mt, 32 bh), 512 thr.
// 3-stage pipeline, one sync/iter. dyn smem 154624:
// per stage 51200 (AH 0 (20480) AL 20480 BH 40960 (5120) BL 46080); inv_s @153600
// ===========================================================================
#define CTX_BUF 51200
__global__ void __launch_bounds__(512) ctx_mma_kernel(float* __restrict__ attn)
{
    extern __shared__ char sm[];
    const uint32_t sb = smem_u32(sm);
    float* inv_s = (float*)(sm + 153600);

    const int bh = blockIdx.y, tx = threadIdx.x, w = tx >> 5, lane = tx & 31;
    const int m0 = blockIdx.x * 256;
    const int wm0 = (w & 7) * 32, wn0 = (w >> 3) * 32;
    const uint32_t laneOfs = (lane & 15) * STRIDE + (lane >> 4) * 16;

    const char* SH = (const char*)g_sc_hi + (size_t)bh * Ss * 4096;
    const char* SL = (const char*)g_sc_lo + (size_t)bh * Ss * 4096;
    const char* VTH = (const char*)g_vt_hi + (size_t)bh * DK * 4096;
    const char* VTL = (const char*)g_vt_lo + (size_t)bh * DK * 4096;

    if (tx < 256) inv_s[tx] = 1.0f / g_rowsum[(size_t)bh * Ss + m0 + tx];

    const int arow = tx >> 1, acb = (tx & 1) * 32;       // A: 256 rows x 2 chunks32
    const int bpl = tx >> 8, brow = (tx & 255) >> 2, bcb = (tx & 3) * 16;
    const size_t gar = (size_t)(m0 + arow) * 4096 + acb;
    const size_t gbr = (size_t)brow * 4096 + bcb;
    const char* VB = bpl ? VTL : VTH;
    const uint32_t dsta = sb + arow * STRIDE + acb;
    const uint32_t dstb = sb + 40960 + bpl * 5120 + brow * STRIDE + bcb;

    #pragma unroll
    for (int p = 0; p < 2; p++) {
        const uint32_t da = dsta + p * CTX_BUF;
        cpa16(da + 0,          SH + gar + p * 64);
        cpa16(da + 16,         SH + gar + p * 64 + 16);
        cpa16(da + 20480,      SL + gar + p * 64);
        cpa16(da + 20480 + 16, SL + gar + p * 64 + 16);
        cpa16(dstb + p * CTX_BUF, VB + gbr + p * 64);
        CPA_COMMIT();
    }

    float c[2][4][4] = {};

    for (int it = 0; it < 64; it++) {
        if (it == 63) { CPA_WAIT0(); } else { CPA_WAIT1(); }
        __syncthreads();
        if (it + 2 < 64) {
            const int k2 = (it + 2) * 64;
            const uint32_t da = dsta + ((it + 2) % 3) * CTX_BUF;
            cpa16(da + 0,          SH + gar + k2);
            cpa16(da + 16,         SH + gar + k2 + 16);
            cpa16(da + 20480,      SL + gar + k2);
            cpa16(da + 20480 + 16, SL + gar + k2 + 16);
            cpa16(dstb + ((it + 2) % 3) * CTX_BUF, VB + gbr + k2);
            CPA_COMMIT();
        }
        const int st = it % 3;
        const uint32_t cur = sb + st * CTX_BUF;
        const int k0 = it * 32;

        // write normalized attn for this 256x32 block from smem
        #pragma unroll
        for (int j = 0; j < 4; j++) {
            const int idx = tx + j * 512;
            const int row = idx >> 3, c4 = (idx & 7) * 4;
            uint2 hv = *(uint2*)(sm + st * CTX_BUF + row * STRIDE + c4 * 2);
            uint2 lv = *(uint2*)(sm + st * CTX_BUF + 20480 + row * STRIDE + c4 * 2);
            const float is = inv_s[row];
            float4 o;
            o.x = (__uint_as_float(hv.x << 16)         + __uint_as_float(lv.x << 16)) * is;
            o.y = (__uint_as_float(hv.x & 0xFFFF0000u) + __uint_as_float(lv.x & 0xFFFF0000u)) * is;
            o.z = (__uint_as_float(hv.y << 16)         + __uint_as_float(lv.y << 16)) * is;
            o.w = (__uint_as_float(hv.y & 0xFFFF0000u) + __uint_as_float(lv.y & 0xFFFF0000u)) * is;
            *(float4*)&attn[((size_t)bh * Ss + m0 + row) * Ss + k0 + c4] = o;
        }

        wtile_k16<2>(c, cur, cur + 20480, cur + 40960, cur + 46080, wm0, wn0, 0,  laneOfs, STRIDE);
        wtile_k16<2>(c, cur, cur + 20480, cur + 40960, cur + 46080, wm0, wn0, 16, laneOfs, STRIDE);
    }

    // epilogue: scale by inv_s, split, store ctx planes
    const int g = lane >> 2, t2 = (lane & 3) * 2;
    const int b = bh >> 4, h = bh & (Hh - 1);
    #pragma unroll
    for (int mf = 0; mf < 2; mf++)
        #pragma unroll
        for (int nf = 0; nf < 4; nf++) {
            const int dc = wn0 + nf * 8 + t2;
            #pragma unroll
            for (int rr = 0; rr < 2; rr++) {
                const int sl = wm0 + mf * 16 + g + rr * 8;   // local row
                const float is = inv_s[sl];
                float f0 = c[mf][nf][2 * rr] * is;
                float f1 = c[mf][nf][2 * rr + 1] * is;
                uint32_t hw = pk2(f0, f1);
                float a0 = __uint_as_float(hw << 16), a1 = __uint_as_float(hw & 0xFFFF0000u);
                uint32_t lw = pk2(f0 - a0, f1 - a1);
                const size_t eo = (((size_t)(b * Ss + m0 + sl)) * Dd + h * DK + dc) * 2;
                *(uint32_t*)((char*)g_ctx_hi + eo) = hw;
                *(uint32_t*)((char*)g_ctx_lo + eo) = lw;
            }
        }
}

// ===========================================================================
// out: out = ctx @ W_o + b_o fp32. grid (8 nt, 32 mt), 512 thr, dyn smem 122880
// 3-stage pipeline, one sync/iter.
// ===========================================================================
__global__ void __launch_bounds__(512) out_mma_kernel(
    const float* __restrict__ bias, float* __restrict__ out)
{
    extern __shared__ char sm[];
    const uint32_t sb = smem_u32(sm);

    const int tx = threadIdx.x, w = tx >> 5, lane = tx & 31;
    const int n0 = blockIdx.x * 128, m0 = blockIdx.y * 128;
    const int wm0 = (w & 3) * 32, wn0 = (w >> 2) * 32;
    const uint32_t laneOfs = (lane & 15) * STRIDE + (lane >> 4) * 16;

    const char* AH = (const char*)g_ctx_hi;
    const char* AL = (const char*)g_ctx_lo;
    const char* WtH = (const char*)g_wt_hi[3];
    const char* WtL = (const char*)g_wt_lo[3];

    const int lrow = tx >> 2, lcb = (tx & 3) * 16;
    const size_t gar = (size_t)(m0 + lrow) * 2048 + lcb;
    const size_t gwr = (size_t)(n0 + lrow) * 2048 + lcb;
    const uint32_t dst = sb + lrow * STRIDE + lcb;

    float c[2][4][4] = {};

    #pragma unroll
    for (int p = 0; p < 2; p++) {
        const uint32_t d = dst + p * QKV_BUF;
        cpa16(d + 0,     AH  + gar + p * 64);
        cpa16(d + 10240, AL  + gar + p * 64);
        cpa16(d + 20480, WtH + gwr + p * 64);
        cpa16(d + 30720, WtL + gwr + p * 64);
        CPA_COMMIT();
    }

    for (int it = 0; it < 32; it++) {
        if (it == 31) { CPA_WAIT0(); } else { CPA_WAIT1(); }
        __syncthreads();
        if (it + 2 < 32) {
            const uint32_t d = dst + ((it + 2) % 3) * QKV_BUF;
            const int k2 = (it + 2) * 64;
            cpa16(d + 0,     AH  + gar + k2);
            cpa16(d + 10240, AL  + gar + k2);
            cpa16(d + 20480, WtH + gwr + k2);
            cpa16(d + 30720, WtL + gwr + k2);
            CPA_COMMIT();
        }
        const uint32_t cur = sb + (it % 3) * QKV_BUF;
        wtile_k16<2>(c, cur, cur + 10240, cur + 20480, cur + 30720, wm0, wn0, 0,  laneOfs, STRIDE);
        wtile_k16<2>(c, cur, cur + 10240, cur + 20480, cur + 30720, wm0, wn0, 16, laneOfs, STRIDE);
    }

    const int g = lane >> 2, t2 = (lane & 3) * 2;
    #pragma unroll
    for (int mf = 0; mf < 2; mf++)
        #pragma unroll
        for (int nf = 0; nf < 4; nf++) {
            const int n = n0 + wn0 + nf * 8 + t2;
            const float bf0 = bias[n], bf1 = bias[n + 1];
            #pragma unroll
            for (int rr = 0; rr < 2; rr++) {
                const int m = m0 + wm0 + mf * 16 + g + rr * 8;
                float2 val = make_float2(c[mf][nf][2 * rr] + bf0,
                                         c[mf][nf][2 * rr + 1] + bf1);
                *(float2*)&out[(size_t)m * Dd + n] = val;
            }
        }
}

// ===========================================================================
extern "C" void kernel_launch(void* const* d_in, const int* in_sizes, int n_in,
                              void* d_out, int out_size)
{
    const float* q   = (const float*)d_in[0];
    const float* k   = (const float*)d_in[1];
    const float* v   = (const float*)d_in[2];
    const float* W_q = (const float*)d_in[3];
    const float* b_q = (const float*)d_in[4];
    const float* W_k = (const float*)d_in[5];
    const float* b_k = (const float*)d_in[6];
    const float* W_v = (const float*)d_in[7];
    const float* b_v = (const float*)d_in[8];
    const float* W_o = (const float*)d_in[9];
    const float* b_o = (const float*)d_in[10];

    float* out  = (float*)d_out;
    float* attn = out + (size_t)Bb * Ss * Dd;

    static int smem_set = 0;
    if (!smem_set) {
        cudaFuncSetAttribute(qkv_mma_kernel,    cudaFuncAttributeMaxDynamicSharedMemorySize, 122880);
        cudaFuncSetAttribute(scores_mma_kernel, cudaFuncAttributeMaxDynamicSharedMemorySize, 74240);
        cudaFuncSetAttribute(ctx_mma_kernel,    cudaFuncAttributeMaxDynamicSharedMemorySize, 154624);
        cudaFuncSetAttribute(out_mma_kernel,    cudaFuncAttributeMaxDynamicSharedMemorySize, 122880);
        smem_set = 1;
    }

    prep_w_kernel<<<dim3(16, 32, 4), 256>>>(W_q, W_k, W_v, W_o);
    prep_x_kernel<<<dim3(4096, 3), 256>>>(q, k, v);
    zero_rs_kernel<<<64, 256>>>();
    qkv_mma_kernel<<<dim3(8, 32, 3), 512, 122880>>>(b_q, b_k, b_v);
    vt_kernel<<<dim3(32, 2, 32), 256>>>();
    scores_mma_kernel<<<dim3(16, 16, 32), 512, 74240>>>();
    ctx_mma_kernel<<<dim3(8, 32), 512, 154624>>>(attn);
    out_mma_kernel<<<dim3(8, 32), 512, 122880>>>(b_o, out);
}